// round 11
// baseline (speedup 1.0000x reference)
#include <cuda_runtime.h>
#include <cuda_bf16.h>
#include <math.h>
#include <stdint.h>

// ---------------- scratch (static device memory; no allocations) ----------------
__device__ __nv_bfloat16 g_xb[8192 * 1024];
__device__ __nv_bfloat16 g_wqkv[768 * 256];
__device__ float         g_bqkv[768];
__device__ __nv_bfloat16 g_wvecb[512 * 256];
__device__ __nv_bfloat16 g_wgb[256 * 512];
__device__ __nv_bfloat16 g_wob[768 * 256];
__device__ __nv_bfloat16 g_qb[8192 * 256];
__device__ __nv_bfloat16 g_kb[8192 * 256];
__device__ __nv_bfloat16 g_vb[8192 * 256];
__device__ __nv_bfloat16 g_projb[24576 * 512];
__device__ __nv_bfloat16 g_invb[8192 * 512];
__device__ __nv_bfloat16 g_xoutb[8192 * 256];
__device__ float g_dot[8192 * 256];
__device__ float g_norm[8192 * 256];
__device__ __nv_bfloat16 g_gateb[8192 * 256];
__device__ __nv_bfloat16 g_vaggrb[8192 * 768];
__device__ __nv_bfloat16 g_ob[8192 * 768];

// ---------------- helpers ----------------
__device__ __forceinline__ uint32_t pack_bf2(float lo, float hi) {
    uint32_t r;
    asm("cvt.rn.bf16x2.f32 %0, %1, %2;" : "=r"(r) : "f"(hi), "f"(lo));
    return r;
}
__device__ __forceinline__ float2 unpack_bf2(uint32_t u) {
    __nv_bfloat162 h = *reinterpret_cast<__nv_bfloat162*>(&u);
    return __bfloat1622float2(h);
}
__device__ __forceinline__ void mma_bf16(float* c,
    uint32_t a0, uint32_t a1, uint32_t a2, uint32_t a3,
    uint32_t b0, uint32_t b1)
{
    asm volatile("mma.sync.aligned.m16n8k16.row.col.f32.bf16.bf16.f32 "
        "{%0,%1,%2,%3}, {%4,%5,%6,%7}, {%8,%9}, {%0,%1,%2,%3};"
        : "+f"(c[0]), "+f"(c[1]), "+f"(c[2]), "+f"(c[3])
        : "r"(a0), "r"(a1), "r"(a2), "r"(a3), "r"(b0), "r"(b1));
}
__device__ __forceinline__ void ldsm4(uint32_t& r0, uint32_t& r1, uint32_t& r2, uint32_t& r3,
                                      const void* p)
{
    uint32_t a = (uint32_t)__cvta_generic_to_shared(p);
    asm volatile("ldmatrix.sync.aligned.m8n8.x4.shared.b16 {%0,%1,%2,%3}, [%4];"
        : "=r"(r0), "=r"(r1), "=r"(r2), "=r"(r3) : "r"(a));
}
__device__ __forceinline__ void ldsm4t(uint32_t& r0, uint32_t& r1, uint32_t& r2, uint32_t& r3,
                                       const void* p)
{
    uint32_t a = (uint32_t)__cvta_generic_to_shared(p);
    asm volatile("ldmatrix.sync.aligned.m8n8.x4.trans.shared.b16 {%0,%1,%2,%3}, [%4];"
        : "=r"(r0), "=r"(r1), "=r"(r2), "=r"(r3) : "r"(a));
}
__device__ __forceinline__ void cpa16(uint32_t dst, const void* src) {
    asm volatile("cp.async.cg.shared.global [%0], [%1], 16;" :: "r"(dst), "l"(src));
}
__device__ __forceinline__ void cpa_commit() {
    asm volatile("cp.async.commit_group;");
}
template <int N>
__device__ __forceinline__ void cpa_wait() {
    asm volatile("cp.async.wait_group %0;" :: "n"(N));
}

// ---------------- fused prep: x -> bf16, weights -> bf16 ----------------
__device__ __forceinline__ void cvt4(__nv_bfloat16* dst, const float* src) {
    float4 f = *(const float4*)src;
    uint32_t* d = (uint32_t*)dst;
    d[0] = pack_bf2(f.x, f.y);
    d[1] = pack_bf2(f.z, f.w);
}
__global__ __launch_bounds__(256) void prep_all_k(
    const float* __restrict__ x,
    const float* __restrict__ Wq, const float* __restrict__ Wk, const float* __restrict__ Wv,
    const float* __restrict__ Wvec, const float* __restrict__ Wg, const float* __restrict__ Wo,
    const float* __restrict__ bq, const float* __restrict__ bk, const float* __restrict__ bv)
{
    int bid = blockIdx.x;
    if (bid < 8192) {
        int j = threadIdx.x << 2;
        float4 f = *(const float4*)(x + (size_t)bid * 1024 + j);
        uint32_t* d = (uint32_t*)g_xb + (((size_t)bid * 1024 + j) >> 1);
        d[0] = pack_bf2(f.x, f.y);
        d[1] = pack_bf2(f.z, f.w);
        return;
    }
    long i = (long)((bid - 8192) * 256 + threadIdx.x) << 2;
    if (i < 65536)        cvt4(g_wqkv + i, Wq + i);
    else if (i < 131072)  cvt4(g_wqkv + i, Wk + (i - 65536));
    else if (i < 196608)  cvt4(g_wqkv + i, Wv + (i - 131072));
    else if (i < 327680)  cvt4(g_wvecb + (i - 196608), Wvec + (i - 196608));
    else if (i < 458752)  cvt4(g_wgb + (i - 327680), Wg + (i - 327680));
    else if (i < 655360)  cvt4(g_wob + (i - 458752), Wo + (i - 458752));
    else if (i < 656128) {
        int j = (int)(i - 655360);
        const float* src = (j < 256) ? (bq + j) : (j < 512 ? bk + (j - 256) : bv + (j - 512));
        *(float4*)(g_bqkv + j) = *(const float4*)src;
    }
}

// ---------------- bf16 cp.async GEMM: C = A @ W^T + bias ----------------
// BM=128, BN=128, BK=32; 256 threads = 8 warps (2 m x 4 n), warp tile 64x32.
template <int ROWMAP, int OUT>
__global__ __launch_bounds__(256, 2) void gemm3_k(
    const __nv_bfloat16* __restrict__ Ab, const __nv_bfloat16* __restrict__ Wb,
    const float* __restrict__ bias, void* __restrict__ Cv,
    void* __restrict__ Cv2, void* __restrict__ Cv3,
    int K, int lda, int ldc)
{
    __shared__ uint32_t SA[2][128][20];
    __shared__ uint32_t SB[2][128][20];

    const int tid = threadIdx.x;
    const int w = tid >> 5, lane = tid & 31;
    const int l4 = lane >> 2, lm4 = lane & 3, sel = lane >> 3;
    const int wr = w >> 2, wc = w & 3;
    const int bm = blockIdx.y << 7, bn = blockIdx.x << 7;

    const int r0 = tid >> 2, off = tid & 3;
    const __nv_bfloat16 *pa0, *pa1;
    if (ROWMAP == 0) {
        pa0 = Ab + (size_t)(bm + r0) * lda + off * 8;
        pa1 = Ab + (size_t)(bm + r0 + 64) * lda + off * 8;
    } else {
        int g0 = bm + r0, m0 = g0 / 3, c0 = g0 - 3 * m0;
        int g1 = bm + r0 + 64, m1 = g1 / 3, c1 = g1 - 3 * m1;
        pa0 = Ab + (size_t)m0 * 1024 + (size_t)(c0 + 1) * 256 + off * 8;
        pa1 = Ab + (size_t)m1 * 1024 + (size_t)(c1 + 1) * 256 + off * 8;
    }
    const __nv_bfloat16* pb0 = Wb + (size_t)(bn + r0) * K + off * 8;
    const __nv_bfloat16* pb1 = Wb + (size_t)(bn + r0 + 64) * K + off * 8;

    const uint32_t saA = (uint32_t)__cvta_generic_to_shared(&SA[0][0][0]);
    const uint32_t saB = (uint32_t)__cvta_generic_to_shared(&SB[0][0][0]);
    const uint32_t dA0 = saA + (r0 * 20 + off * 4) * 4;
    const uint32_t dA1 = saA + ((r0 + 64) * 20 + off * 4) * 4;
    const uint32_t dB0 = saB + (r0 * 20 + off * 4) * 4;
    const uint32_t dB1 = saB + ((r0 + 64) * 20 + off * 4) * 4;
    const uint32_t stB = 2560 * 4;

    float acc[4][4][4];
#pragma unroll
    for (int mt = 0; mt < 4; mt++)
#pragma unroll
        for (int nt = 0; nt < 4; nt++)
#pragma unroll
            for (int e = 0; e < 4; e++) acc[mt][nt][e] = 0.f;

    const int niter = K >> 5;

#pragma unroll
    for (int st = 0; st < 2; st++) {
        int k0 = st << 5;
        cpa16(dA0 + st * stB, pa0 + k0);
        cpa16(dA1 + st * stB, pa1 + k0);
        cpa16(dB0 + st * stB, pb0 + k0);
        cpa16(dB1 + st * stB, pb1 + k0);
        cpa_commit();
    }

    for (int it = 0; it < niter; it++) {
        if (it + 1 < niter) cpa_wait<1>(); else cpa_wait<0>();
        __syncthreads();
        const int st = it & 1;

#pragma unroll
        for (int ks = 0; ks < 2; ks++) {
            uint32_t af[4][4];
#pragma unroll
            for (int mt = 0; mt < 4; mt++)
                ldsm4(af[mt][0], af[mt][1], af[mt][2], af[mt][3],
                      &SA[st][wr * 64 + mt * 16 + (lane & 15)][ks * 8 + (lane >> 4) * 4]);
            uint32_t bf[4][2];
#pragma unroll
            for (int jp = 0; jp < 2; jp++) {
                uint32_t b0, b1, b2, b3;
                ldsm4(b0, b1, b2, b3,
                      &SB[st][wc * 32 + (jp * 2 + (sel >> 1)) * 8 + (lane & 7)][ks * 8 + (sel & 1) * 4]);
                bf[jp * 2][0] = b0; bf[jp * 2][1] = b1;
                bf[jp * 2 + 1][0] = b2; bf[jp * 2 + 1][1] = b3;
            }
#pragma unroll
            for (int mt = 0; mt < 4; mt++)
#pragma unroll
                for (int nt = 0; nt < 4; nt++)
                    mma_bf16(acc[mt][nt], af[mt][0], af[mt][1], af[mt][2], af[mt][3],
                             bf[nt][0], bf[nt][1]);
        }
        __syncthreads();
        if (it + 2 < niter) {
            int k0 = (it + 2) << 5;
            cpa16(dA0 + st * stB, pa0 + k0);
            cpa16(dA1 + st * stB, pa1 + k0);
            cpa16(dB0 + st * stB, pb0 + k0);
            cpa16(dB1 + st * stB, pb1 + k0);
            cpa_commit();
        }
    }

    const float qscale = 0.17677669529663687f;
#pragma unroll
    for (int mt = 0; mt < 4; mt++) {
#pragma unroll
        for (int nt = 0; nt < 4; nt++) {
            int c = bn + wc * 32 + nt * 8 + lm4 * 2;
            float bx = 0.f, by = 0.f;
            if (bias) { bx = bias[c]; by = bias[c + 1]; }
#pragma unroll
            for (int half = 0; half < 2; half++) {
                int r = bm + wr * 64 + mt * 16 + l4 + half * 8;
                float vx = acc[mt][nt][half * 2 + 0] + bx;
                float vy = acc[mt][nt][half * 2 + 1] + by;
                if (OUT == 0) {
                    float2 v2; v2.x = vx; v2.y = vy;
                    *(float2*)((float*)Cv + (size_t)r * ldc + c) = v2;
                } else if (OUT == 5) {
                    vx = 1.f / (1.f + __expf(-vx));
                    vy = 1.f / (1.f + __expf(-vy));
                    ((uint32_t*)Cv)[((size_t)r * ldc + c) >> 1] = pack_bf2(vx, vy);
                } else if (OUT == 1) {
                    ((uint32_t*)Cv)[((size_t)r * ldc + c) >> 1] = pack_bf2(vx, vy);
                } else {  // OUT == 4: qkv split
                    int third = c >> 8, lc = c & 255;
                    void* dst = (third == 0) ? Cv : (third == 1 ? Cv2 : Cv3);
                    if (third == 0) { vx *= qscale; vy *= qscale; }
                    ((uint32_t*)dst)[((size_t)r * 256 + lc) >> 1] = pack_bf2(vx, vy);
                }
            }
        }
    }
}

// ---------------- invariants ----------------
__global__ __launch_bounds__(256) void inv_k(
    const float* __restrict__ alpha_dot, const float* __restrict__ alpha_norm)
{
    int idx = blockIdx.x * 256 + threadIdx.x;
    int m = idx >> 6, j = (idx & 63) << 2;
    const uint32_t* xb32 = (const uint32_t*)g_xb;
    float d0 = 0.f, d1 = 0.f, d2 = 0.f, d3 = 0.f;
    float n0 = 0.f, n1 = 0.f, n2 = 0.f, n3 = 0.f;
#pragma unroll
    for (int c = 0; c < 3; c++) {
        const uint32_t* pr = (const uint32_t*)(g_projb + (size_t)(m * 3 + c) * 512);
        uint32_t a0 = pr[(j >> 1)], a1 = pr[(j >> 1) + 1];
        uint32_t b0 = pr[128 + (j >> 1)], b1 = pr[129 + (j >> 1)];
        float2 fa0 = unpack_bf2(a0), fa1 = unpack_bf2(a1);
        float2 fb0 = unpack_bf2(b0), fb1 = unpack_bf2(b1);
        d0 += fa0.x * fb0.x; d1 += fa0.y * fb0.y;
        d2 += fa1.x * fb1.x; d3 += fa1.y * fb1.y;
        uint32_t x0 = xb32[((size_t)m * 1024 + 256 + c * 256 + j) >> 1];
        uint32_t x1 = xb32[(((size_t)m * 1024 + 256 + c * 256 + j) >> 1) + 1];
        float2 fx0 = unpack_bf2(x0), fx1 = unpack_bf2(x1);
        n0 += fx0.x * fx0.x; n1 += fx0.y * fx0.y;
        n2 += fx1.x * fx1.x; n3 += fx1.y * fx1.y;
    }
    n0 = sqrtf(n0); n1 = sqrtf(n1); n2 = sqrtf(n2); n3 = sqrtf(n3);
    float4 dv; dv.x = d0; dv.y = d1; dv.z = d2; dv.w = d3;
    float4 nv; nv.x = n0; nv.y = n1; nv.z = n2; nv.w = n3;
    *(float4*)(g_dot + (size_t)m * 256 + j) = dv;
    *(float4*)(g_norm + (size_t)m * 256 + j) = nv;
    float ad = alpha_dot[0], an = alpha_norm[0];
    uint32_t* inv32 = (uint32_t*)g_invb;
    inv32[((size_t)m * 512 + j) >> 1]       = pack_bf2(ad * d0, ad * d1);
    inv32[(((size_t)m * 512 + j) >> 1) + 1] = pack_bf2(ad * d2, ad * d3);
    inv32[((size_t)m * 512 + 256 + j) >> 1]       = pack_bf2(an * n0, an * n1);
    inv32[(((size_t)m * 512 + 256 + j) >> 1) + 1] = pack_bf2(an * n2, an * n3);
}

// ---------------- flash attention v6: reg double-buffer, 2-stage smem, ONE sync/iter ----
// BQ=128, grid (16, 8, 4), 256 threads (8 warps); each warp: 16 q-rows x all keys.
// V is row-major [key][dv]; B-fragments via ldmatrix.trans. Fixed-max softmax.
__global__ __launch_bounds__(256, 1) void flash6_k()
{
    __shared__ __align__(16) char raw[45056];   // 2 stages x (Ks 5120 + Vs 17408)
    uint32_t (*bufu)[66] = (uint32_t(*)[66])raw;

    const int qt = blockIdx.x, h = blockIdx.y, b = blockIdx.z;
    const int tid = threadIdx.x;
    const int w = tid >> 5, lane = tid & 31;
    const int l4 = lane >> 2, lm4 = lane & 3, sel = lane >> 3;
    const int r1 = w * 16 + l4;

    uint32_t qf[2][4];
    {
        const uint32_t* qb = (const uint32_t*)g_qb;
        const uint32_t* q1 = qb + (size_t)(b * 2048 + qt * 128 + r1) * 128 + h * 16;
        const uint32_t* q2 = q1 + 8 * 128;
        qf[0][0] = q1[lm4];     qf[0][1] = q2[lm4];
        qf[0][2] = q1[lm4 + 4]; qf[0][3] = q2[lm4 + 4];
        qf[1][0] = q1[8 + lm4];     qf[1][1] = q2[8 + lm4];
        qf[1][2] = q1[8 + lm4 + 4]; qf[1][3] = q2[8 + lm4 + 4];
    }

    float l1 = 0.f, l2 = 0.f;
    float o[16][4];
#pragma unroll
    for (int nt = 0; nt < 16; nt++)
#pragma unroll
        for (int e = 0; e < 4; e++) o[nt][e] = 0.f;

    // loader geometry: thread -> key row (tid>>2), 16B segment (tid&3)
    const int krow = tid >> 2, kseg = tid & 3;
    const uint32_t* kbg = (const uint32_t*)g_kb;
    const uint32_t* vbg = (const uint32_t*)g_vb;
    const uint32_t* xbg = (const uint32_t*)g_xb;

    uint4 kreg;
    uint4 vreg[4];
    auto load_tile = [&](int kt2) {
        int tok = b * 2048 + kt2 * 64 + krow;
        kreg = *(const uint4*)(kbg + (size_t)tok * 128 + h * 16 + kseg * 4);
        const uint32_t* vsrc;
        if (kseg == 0) vsrc = vbg + (size_t)tok * 128 + h * 16;
        else           vsrc = xbg + (size_t)tok * 512 + 128 + (kseg - 1) * 128 + h * 16;
#pragma unroll
        for (int i = 0; i < 4; i++)
            vreg[i] = *(const uint4*)(vsrc + i * 4);
    };
    auto store_tile = [&](int st) {
        char* stage = raw + st * 22528;
        *(uint4*)(stage + (krow * 20 + kseg * 4) * 4) = kreg;
        uint4* vd = (uint4*)(stage + 5120 + (krow * 68 + kseg * 16) * 4);
#pragma unroll
        for (int i = 0; i < 4; i++) vd[i] = vreg[i];
    };

    // prologue: tile0 -> stage0, tile1 staged in regs
    load_tile(0);
    store_tile(0);
    load_tile(1);
    __syncthreads();

    for (int kt = 0; kt < 32; kt++) {
        // store tile kt+1 into stage (kt+1)&1 (read next iter); safe: that stage's
        // readers (iter kt-1) passed the sync at end of iter kt-1.
        if (kt + 1 < 32) store_tile((kt + 1) & 1);
        if (kt + 2 < 32) load_tile(kt + 2);

        const char* stage = raw + (kt & 1) * 22528;
        const char* Kst = stage;            // [64][20] u32
        const char* Vst = stage + 5120;     // [64][68] u32

        // ---- S = Q K^T : 16 rows x 64 keys ----
        float s[8][4];
#pragma unroll
        for (int nt = 0; nt < 8; nt++)
#pragma unroll
            for (int e = 0; e < 4; e++) s[nt][e] = 0.f;

#pragma unroll
        for (int ks = 0; ks < 2; ks++) {
#pragma unroll
            for (int jp = 0; jp < 4; jp++) {
                int ntE = jp * 2 + (sel >> 1);
                int rowE = ntE * 8 + (lane & 7);
                int col = ks * 8 + (sel & 1) * 4;
                uint32_t b0, b1, b2, b3;
                ldsm4(b0, b1, b2, b3, Kst + rowE * 80 + col * 4);
                mma_bf16(s[jp * 2 + 0], qf[ks][0], qf[ks][1], qf[ks][2], qf[ks][3], b0, b1);
                mma_bf16(s[jp * 2 + 1], qf[ks][0], qf[ks][1], qf[ks][2], qf[ks][3], b2, b3);
            }
        }

        // ---- p = exp(s), per-thread row sums, pack A-fragments ----
        uint32_t pa[4][4];
#pragma unroll
        for (int ks = 0; ks < 4; ks++) {
            float p00 = __expf(s[2 * ks][0]);
            float p01 = __expf(s[2 * ks][1]);
            float p02 = __expf(s[2 * ks][2]);
            float p03 = __expf(s[2 * ks][3]);
            float p10 = __expf(s[2 * ks + 1][0]);
            float p11 = __expf(s[2 * ks + 1][1]);
            float p12 = __expf(s[2 * ks + 1][2]);
            float p13 = __expf(s[2 * ks + 1][3]);
            l1 += p00 + p01 + p10 + p11;
            l2 += p02 + p03 + p12 + p13;
            pa[ks][0] = pack_bf2(p00, p01);
            pa[ks][1] = pack_bf2(p02, p03);
            pa[ks][2] = pack_bf2(p10, p11);
            pa[ks][3] = pack_bf2(p12, p13);
        }

        // ---- O += P V : B-fragments via ldsm.trans from row-major V ----
#pragma unroll
        for (int ks = 0; ks < 4; ks++) {
#pragma unroll
            for (int jj = 0; jj < 8; jj++) {
                int vrow = ks * 16 + (sel & 1) * 8 + (lane & 7);
                int vcol = jj * 8 + (sel >> 1) * 4;
                uint32_t b0, b1, b2, b3;
                ldsm4t(b0, b1, b2, b3, Vst + vrow * 272 + vcol * 4);
                mma_bf16(o[2 * jj + 0], pa[ks][0], pa[ks][1], pa[ks][2], pa[ks][3], b0, b1);
                mma_bf16(o[2 * jj + 1], pa[ks][0], pa[ks][1], pa[ks][2], pa[ks][3], b2, b3);
            }
        }

        __syncthreads();
    }

    // ---- row-sum reduce (warp-local) ----
    l1 += __shfl_xor_sync(0xffffffffu, l1, 1);
    l1 += __shfl_xor_sync(0xffffffffu, l1, 2);
    l2 += __shfl_xor_sync(0xffffffffu, l2, 1);
    l2 += __shfl_xor_sync(0xffffffffu, l2, 2);
    float w1 = 1.f / l1, w2 = 1.f / l2;

    // ---- two-phase staged writeout through smem ----
#pragma unroll
    for (int ph = 0; ph < 2; ph++) {
        __syncthreads();
        if ((w >> 2) == ph) {
            int lr1 = (w & 3) * 16 + l4, lr2 = lr1 + 8;
#pragma unroll
            for (int nt = 0; nt < 16; nt++) {
                bufu[lr1][nt * 4 + lm4] = pack_bf2(o[nt][0] * w1, o[nt][1] * w1);
                bufu[lr2][nt * 4 + lm4] = pack_bf2(o[nt][2] * w2, o[nt][3] * w2);
            }
        }
        __syncthreads();
        int r = tid >> 2, qtr = tid & 3;
        int tok = b * 2048 + qt * 128 + ph * 64 + r;
        if (qtr == 0) {
            uint32_t* dst = (uint32_t*)g_xoutb + (size_t)tok * 128 + h * 16;
#pragma unroll
            for (int i = 0; i < 16; i++)
                dst[i] = bufu[r][i];
        } else {
            int c = qtr - 1;
            uint32_t* dst = (uint32_t*)g_vaggrb + (((size_t)tok * 768 + c * 256 + h * 32) >> 1);
#pragma unroll
            for (int i = 0; i < 16; i++)
                dst[i] = bufu[r][qtr * 16 + i];
        }
    }
}

// ---------------- final elementwise combine ----------------
__global__ __launch_bounds__(256) void final_k(const float* __restrict__ x, float* __restrict__ out)
{
    int idx = blockIdx.x * blockDim.x + threadIdx.x;
    if (idx >= 8192 * 64) return;
    int m = idx >> 6, j = (idx & 63) << 2;

    const uint32_t* ob = (const uint32_t*)g_ob;
    size_t base = (size_t)m * 768;
    uint32_t u;
    u = ob[(base + j) >> 1];       float2 o1a = unpack_bf2(u);
    u = ob[((base + j) >> 1) + 1]; float2 o1b = unpack_bf2(u);
    u = ob[(base + 256 + j) >> 1];       float2 o2a = unpack_bf2(u);
    u = ob[((base + 256 + j) >> 1) + 1]; float2 o2b = unpack_bf2(u);
    u = ob[(base + 512 + j) >> 1];       float2 o3a = unpack_bf2(u);
    u = ob[((base + 512 + j) >> 1) + 1]; float2 o3b = unpack_bf2(u);

    float4 vd = *(const float4*)(g_dot + (size_t)m * 256 + j);
    float4 vn = *(const float4*)(g_norm + (size_t)m * 256 + j);
    float4 r;
    r.x = vd.x * o1a.x + vn.x * o2a.x + o3a.x;
    r.y = vd.y * o1a.y + vn.y * o2a.y + o3a.y;
    r.z = vd.z * o1b.x + vn.z * o2b.x + o3b.x;
    r.w = vd.w * o1b.y + vn.w * o2b.y + o3b.y;
    *(float4*)(out + (size_t)m * 1024 + j) = r;

    const uint32_t* gb = (const uint32_t*)g_gateb;
    u = gb[((size_t)m * 256 + j) >> 1];       float2 ga = unpack_bf2(u);
    u = gb[(((size_t)m * 256 + j) >> 1) + 1]; float2 gbv = unpack_bf2(u);
    const uint32_t* vab = (const uint32_t*)g_vaggrb;
#pragma unroll
    for (int c = 0; c < 3; c++) {
        size_t xi = (size_t)m * 1024 + 256 + c * 256 + j;
        u = vab[(base + c * 256 + j) >> 1];       float2 va = unpack_bf2(u);
        u = vab[((base + c * 256 + j) >> 1) + 1]; float2 vb = unpack_bf2(u);
        float4 xv = *(const float4*)(x + xi);
        float4 rr;
        rr.x = ga.x * va.x + xv.x;
        rr.y = ga.y * va.y + xv.y;
        rr.z = gbv.x * vb.x + xv.z;
        rr.w = gbv.y * vb.y + xv.w;
        *(float4*)(out + xi) = rr;
    }
}

// ---------------- launch ----------------
extern "C" void kernel_launch(void* const* d_in, const int* in_sizes, int n_in,
                              void* d_out, int out_size)
{
    const float* x    = (const float*)d_in[0];
    const float* Wq   = (const float*)d_in[1];
    const float* bq   = (const float*)d_in[2];
    const float* Wk   = (const float*)d_in[3];
    const float* bk   = (const float*)d_in[4];
    const float* Wv   = (const float*)d_in[5];
    const float* bv   = (const float*)d_in[6];
    const float* Wvec = (const float*)d_in[7];
    const float* Wo   = (const float*)d_in[8];
    const float* bo   = (const float*)d_in[9];
    const float* Wg   = (const float*)d_in[10];
    const float* bg   = (const float*)d_in[11];
    const float* adot = (const float*)d_in[12];
    const float* anrm = (const float*)d_in[13];
    float* out = (float*)d_out;

    void *xbp, *wqkvp, *bqkvp, *wvecp, *wgp, *wop;
    void *qbp, *kbp, *vbp, *projbp, *invbp, *xoutbp, *gatep, *obp;
    cudaGetSymbolAddress(&xbp, g_xb);
    cudaGetSymbolAddress(&wqkvp, g_wqkv);
    cudaGetSymbolAddress(&bqkvp, g_bqkv);
    cudaGetSymbolAddress(&wvecp, g_wvecb);
    cudaGetSymbolAddress(&wgp, g_wgb);
    cudaGetSymbolAddress(&wop, g_wob);
    cudaGetSymbolAddress(&qbp, g_qb);
    cudaGetSymbolAddress(&kbp, g_kb);
    cudaGetSymbolAddress(&vbp, g_vb);
    cudaGetSymbolAddress(&projbp, g_projb);
    cudaGetSymbolAddress(&invbp, g_invb);
    cudaGetSymbolAddress(&xoutbp, g_xoutb);
    cudaGetSymbolAddress(&gatep, g_gateb);
    cudaGetSymbolAddress(&obp, g_ob);

    dim3 blk(256);
    prep_all_k<<<8833, blk>>>(x, Wq, Wk, Wv, Wvec, Wg, Wo, bq, bk, bv);
    // fused q/k/v: M=8192, N=768, K=256
    gemm3_k<0, 4><<<dim3(6, 64), blk>>>(
        (const __nv_bfloat16*)xbp, (const __nv_bfloat16*)wqkvp, (const float*)bqkvp,
        qbp, kbp, vbp, 256, 1024, 256);
    // vec proj: M=24576, N=512, K=256
    gemm3_k<1, 1><<<dim3(4, 192), blk>>>(
        (const __nv_bfloat16*)xbp, (const __nv_bfloat16*)wvecp, nullptr,
        projbp, nullptr, nullptr, 256, 0, 512);
    // invariants
    inv_k<<<2048, blk>>>(adot, anrm);
    // gate: M=8192, N=256, K=512, sigmoid bf16 out
    gemm3_k<0, 5><<<dim3(2, 64), blk>>>(
        (const __nv_bfloat16*)invbp, (const __nv_bfloat16*)wgp, bg,
        gatep, nullptr, nullptr, 512, 512, 256);
    flash6_k<<<dim3(16, 8, 4), blk>>>();
    // Wo: M=8192, N=768, K=256, bf16 out
    gemm3_k<0, 1><<<dim3(6, 64), blk>>>(
        (const __nv_bfloat16*)xoutbp, (const __nv_bfloat16*)wop, bo,
        obp, nullptr, nullptr, 256, 256, 768);
    final_k<<<2048, blk>>>(x, out);
}

// round 12
// speedup vs baseline: 1.1709x; 1.1709x over previous
#include <cuda_runtime.h>
#include <cuda_bf16.h>
#include <math.h>
#include <stdint.h>

// ---------------- scratch (static device memory; no allocations) ----------------
__device__ __nv_bfloat16 g_xb[8192 * 1024];
__device__ __nv_bfloat16 g_wqkv[768 * 256];
__device__ float         g_bqkv[768];
__device__ __nv_bfloat16 g_wvecb[512 * 256];
__device__ __nv_bfloat16 g_wgb[256 * 512];
__device__ __nv_bfloat16 g_wob[768 * 256];
__device__ __nv_bfloat16 g_qb[8192 * 256];
__device__ __nv_bfloat16 g_kb[8192 * 256];
__device__ __nv_bfloat16 g_vb[8192 * 256];
__device__ __nv_bfloat16 g_projb[24576 * 512];
__device__ __nv_bfloat16 g_invb[8192 * 512];
__device__ __nv_bfloat16 g_xoutb[8192 * 256];
__device__ float g_dot[8192 * 256];
__device__ float g_norm[8192 * 256];
__device__ __nv_bfloat16 g_gateb[8192 * 256];
__device__ __nv_bfloat16 g_vaggrb[8192 * 768];
__device__ __nv_bfloat16 g_ob[8192 * 768];

// ---------------- helpers ----------------
__device__ __forceinline__ uint32_t pack_bf2(float lo, float hi) {
    uint32_t r;
    asm("cvt.rn.bf16x2.f32 %0, %1, %2;" : "=r"(r) : "f"(hi), "f"(lo));
    return r;
}
__device__ __forceinline__ float2 unpack_bf2(uint32_t u) {
    __nv_bfloat162 h = *reinterpret_cast<__nv_bfloat162*>(&u);
    return __bfloat1622float2(h);
}
__device__ __forceinline__ void mma_bf16(float* c,
    uint32_t a0, uint32_t a1, uint32_t a2, uint32_t a3,
    uint32_t b0, uint32_t b1)
{
    asm volatile("mma.sync.aligned.m16n8k16.row.col.f32.bf16.bf16.f32 "
        "{%0,%1,%2,%3}, {%4,%5,%6,%7}, {%8,%9}, {%0,%1,%2,%3};"
        : "+f"(c[0]), "+f"(c[1]), "+f"(c[2]), "+f"(c[3])
        : "r"(a0), "r"(a1), "r"(a2), "r"(a3), "r"(b0), "r"(b1));
}
__device__ __forceinline__ void ldsm4(uint32_t& r0, uint32_t& r1, uint32_t& r2, uint32_t& r3,
                                      const void* p)
{
    uint32_t a = (uint32_t)__cvta_generic_to_shared(p);
    asm volatile("ldmatrix.sync.aligned.m8n8.x4.shared.b16 {%0,%1,%2,%3}, [%4];"
        : "=r"(r0), "=r"(r1), "=r"(r2), "=r"(r3) : "r"(a));
}
__device__ __forceinline__ void ldsm4t(uint32_t& r0, uint32_t& r1, uint32_t& r2, uint32_t& r3,
                                       const void* p)
{
    uint32_t a = (uint32_t)__cvta_generic_to_shared(p);
    asm volatile("ldmatrix.sync.aligned.m8n8.x4.trans.shared.b16 {%0,%1,%2,%3}, [%4];"
        : "=r"(r0), "=r"(r1), "=r"(r2), "=r"(r3) : "r"(a));
}
__device__ __forceinline__ void cpa16(uint32_t dst, const void* src) {
    asm volatile("cp.async.cg.shared.global [%0], [%1], 16;" :: "r"(dst), "l"(src));
}
__device__ __forceinline__ void cpa_commit() {
    asm volatile("cp.async.commit_group;");
}
template <int N>
__device__ __forceinline__ void cpa_wait() {
    asm volatile("cp.async.wait_group %0;" :: "n"(N));
}

// ---------------- fused prep: x -> bf16, weights -> bf16 ----------------
__device__ __forceinline__ void cvt4(__nv_bfloat16* dst, const float* src) {
    float4 f = *(const float4*)src;
    uint32_t* d = (uint32_t*)dst;
    d[0] = pack_bf2(f.x, f.y);
    d[1] = pack_bf2(f.z, f.w);
}
__global__ __launch_bounds__(256) void prep_all_k(
    const float* __restrict__ x,
    const float* __restrict__ Wq, const float* __restrict__ Wk, const float* __restrict__ Wv,
    const float* __restrict__ Wvec, const float* __restrict__ Wg, const float* __restrict__ Wo,
    const float* __restrict__ bq, const float* __restrict__ bk, const float* __restrict__ bv)
{
    int bid = blockIdx.x;
    if (bid < 8192) {
        int j = threadIdx.x << 2;
        float4 f = *(const float4*)(x + (size_t)bid * 1024 + j);
        uint32_t* d = (uint32_t*)g_xb + (((size_t)bid * 1024 + j) >> 1);
        d[0] = pack_bf2(f.x, f.y);
        d[1] = pack_bf2(f.z, f.w);
        return;
    }
    long i = (long)((bid - 8192) * 256 + threadIdx.x) << 2;
    if (i < 65536)        cvt4(g_wqkv + i, Wq + i);
    else if (i < 131072)  cvt4(g_wqkv + i, Wk + (i - 65536));
    else if (i < 196608)  cvt4(g_wqkv + i, Wv + (i - 131072));
    else if (i < 327680)  cvt4(g_wvecb + (i - 196608), Wvec + (i - 196608));
    else if (i < 458752)  cvt4(g_wgb + (i - 327680), Wg + (i - 327680));
    else if (i < 655360)  cvt4(g_wob + (i - 458752), Wo + (i - 458752));
    else if (i < 656128) {
        int j = (int)(i - 655360);
        const float* src = (j < 256) ? (bq + j) : (j < 512 ? bk + (j - 256) : bv + (j - 512));
        *(float4*)(g_bqkv + j) = *(const float4*)src;
    }
}

// ---------------- bf16 cp.async GEMM: C = A @ W^T + bias ----------------
// BM=128, BN=128, BK=32; 256 threads = 8 warps (2 m x 4 n), warp tile 64x32.
template <int ROWMAP, int OUT>
__global__ __launch_bounds__(256, 2) void gemm3_k(
    const __nv_bfloat16* __restrict__ Ab, const __nv_bfloat16* __restrict__ Wb,
    const float* __restrict__ bias, void* __restrict__ Cv,
    void* __restrict__ Cv2, void* __restrict__ Cv3,
    int K, int lda, int ldc)
{
    __shared__ uint32_t SA[2][128][20];
    __shared__ uint32_t SB[2][128][20];

    const int tid = threadIdx.x;
    const int w = tid >> 5, lane = tid & 31;
    const int l4 = lane >> 2, lm4 = lane & 3, sel = lane >> 3;
    const int wr = w >> 2, wc = w & 3;
    const int bm = blockIdx.y << 7, bn = blockIdx.x << 7;

    const int r0 = tid >> 2, off = tid & 3;
    const __nv_bfloat16 *pa0, *pa1;
    if (ROWMAP == 0) {
        pa0 = Ab + (size_t)(bm + r0) * lda + off * 8;
        pa1 = Ab + (size_t)(bm + r0 + 64) * lda + off * 8;
    } else {
        int g0 = bm + r0, m0 = g0 / 3, c0 = g0 - 3 * m0;
        int g1 = bm + r0 + 64, m1 = g1 / 3, c1 = g1 - 3 * m1;
        pa0 = Ab + (size_t)m0 * 1024 + (size_t)(c0 + 1) * 256 + off * 8;
        pa1 = Ab + (size_t)m1 * 1024 + (size_t)(c1 + 1) * 256 + off * 8;
    }
    const __nv_bfloat16* pb0 = Wb + (size_t)(bn + r0) * K + off * 8;
    const __nv_bfloat16* pb1 = Wb + (size_t)(bn + r0 + 64) * K + off * 8;

    const uint32_t saA = (uint32_t)__cvta_generic_to_shared(&SA[0][0][0]);
    const uint32_t saB = (uint32_t)__cvta_generic_to_shared(&SB[0][0][0]);
    const uint32_t dA0 = saA + (r0 * 20 + off * 4) * 4;
    const uint32_t dA1 = saA + ((r0 + 64) * 20 + off * 4) * 4;
    const uint32_t dB0 = saB + (r0 * 20 + off * 4) * 4;
    const uint32_t dB1 = saB + ((r0 + 64) * 20 + off * 4) * 4;
    const uint32_t stB = 2560 * 4;

    float acc[4][4][4];
#pragma unroll
    for (int mt = 0; mt < 4; mt++)
#pragma unroll
        for (int nt = 0; nt < 4; nt++)
#pragma unroll
            for (int e = 0; e < 4; e++) acc[mt][nt][e] = 0.f;

    const int niter = K >> 5;

#pragma unroll
    for (int st = 0; st < 2; st++) {
        int k0 = st << 5;
        cpa16(dA0 + st * stB, pa0 + k0);
        cpa16(dA1 + st * stB, pa1 + k0);
        cpa16(dB0 + st * stB, pb0 + k0);
        cpa16(dB1 + st * stB, pb1 + k0);
        cpa_commit();
    }

    for (int it = 0; it < niter; it++) {
        if (it + 1 < niter) cpa_wait<1>(); else cpa_wait<0>();
        __syncthreads();
        const int st = it & 1;

#pragma unroll
        for (int ks = 0; ks < 2; ks++) {
            uint32_t af[4][4];
#pragma unroll
            for (int mt = 0; mt < 4; mt++)
                ldsm4(af[mt][0], af[mt][1], af[mt][2], af[mt][3],
                      &SA[st][wr * 64 + mt * 16 + (lane & 15)][ks * 8 + (lane >> 4) * 4]);
            uint32_t bf[4][2];
#pragma unroll
            for (int jp = 0; jp < 2; jp++) {
                uint32_t b0, b1, b2, b3;
                ldsm4(b0, b1, b2, b3,
                      &SB[st][wc * 32 + (jp * 2 + (sel >> 1)) * 8 + (lane & 7)][ks * 8 + (sel & 1) * 4]);
                bf[jp * 2][0] = b0; bf[jp * 2][1] = b1;
                bf[jp * 2 + 1][0] = b2; bf[jp * 2 + 1][1] = b3;
            }
#pragma unroll
            for (int mt = 0; mt < 4; mt++)
#pragma unroll
                for (int nt = 0; nt < 4; nt++)
                    mma_bf16(acc[mt][nt], af[mt][0], af[mt][1], af[mt][2], af[mt][3],
                             bf[nt][0], bf[nt][1]);
        }
        __syncthreads();
        if (it + 2 < niter) {
            int k0 = (it + 2) << 5;
            cpa16(dA0 + st * stB, pa0 + k0);
            cpa16(dA1 + st * stB, pa1 + k0);
            cpa16(dB0 + st * stB, pb0 + k0);
            cpa16(dB1 + st * stB, pb1 + k0);
            cpa_commit();
        }
    }

    const float qscale = 0.17677669529663687f;
#pragma unroll
    for (int mt = 0; mt < 4; mt++) {
#pragma unroll
        for (int nt = 0; nt < 4; nt++) {
            int c = bn + wc * 32 + nt * 8 + lm4 * 2;
            float bx = 0.f, by = 0.f;
            if (bias) { bx = bias[c]; by = bias[c + 1]; }
#pragma unroll
            for (int half = 0; half < 2; half++) {
                int r = bm + wr * 64 + mt * 16 + l4 + half * 8;
                float vx = acc[mt][nt][half * 2 + 0] + bx;
                float vy = acc[mt][nt][half * 2 + 1] + by;
                if (OUT == 0) {
                    float2 v2; v2.x = vx; v2.y = vy;
                    *(float2*)((float*)Cv + (size_t)r * ldc + c) = v2;
                } else if (OUT == 5) {
                    vx = 1.f / (1.f + __expf(-vx));
                    vy = 1.f / (1.f + __expf(-vy));
                    ((uint32_t*)Cv)[((size_t)r * ldc + c) >> 1] = pack_bf2(vx, vy);
                } else if (OUT == 1) {
                    ((uint32_t*)Cv)[((size_t)r * ldc + c) >> 1] = pack_bf2(vx, vy);
                } else {  // OUT == 4: qkv split
                    int third = c >> 8, lc = c & 255;
                    void* dst = (third == 0) ? Cv : (third == 1 ? Cv2 : Cv3);
                    if (third == 0) { vx *= qscale; vy *= qscale; }
                    ((uint32_t*)dst)[((size_t)r * 256 + lc) >> 1] = pack_bf2(vx, vy);
                }
            }
        }
    }
}

// ---------------- invariants ----------------
__global__ __launch_bounds__(256) void inv_k(
    const float* __restrict__ alpha_dot, const float* __restrict__ alpha_norm)
{
    int idx = blockIdx.x * 256 + threadIdx.x;
    int m = idx >> 6, j = (idx & 63) << 2;
    const uint32_t* xb32 = (const uint32_t*)g_xb;
    float d0 = 0.f, d1 = 0.f, d2 = 0.f, d3 = 0.f;
    float n0 = 0.f, n1 = 0.f, n2 = 0.f, n3 = 0.f;
#pragma unroll
    for (int c = 0; c < 3; c++) {
        const uint32_t* pr = (const uint32_t*)(g_projb + (size_t)(m * 3 + c) * 512);
        uint32_t a0 = pr[(j >> 1)], a1 = pr[(j >> 1) + 1];
        uint32_t b0 = pr[128 + (j >> 1)], b1 = pr[129 + (j >> 1)];
        float2 fa0 = unpack_bf2(a0), fa1 = unpack_bf2(a1);
        float2 fb0 = unpack_bf2(b0), fb1 = unpack_bf2(b1);
        d0 += fa0.x * fb0.x; d1 += fa0.y * fb0.y;
        d2 += fa1.x * fb1.x; d3 += fa1.y * fb1.y;
        uint32_t x0 = xb32[((size_t)m * 1024 + 256 + c * 256 + j) >> 1];
        uint32_t x1 = xb32[(((size_t)m * 1024 + 256 + c * 256 + j) >> 1) + 1];
        float2 fx0 = unpack_bf2(x0), fx1 = unpack_bf2(x1);
        n0 += fx0.x * fx0.x; n1 += fx0.y * fx0.y;
        n2 += fx1.x * fx1.x; n3 += fx1.y * fx1.y;
    }
    n0 = sqrtf(n0); n1 = sqrtf(n1); n2 = sqrtf(n2); n3 = sqrtf(n3);
    float4 dv; dv.x = d0; dv.y = d1; dv.z = d2; dv.w = d3;
    float4 nv; nv.x = n0; nv.y = n1; nv.z = n2; nv.w = n3;
    *(float4*)(g_dot + (size_t)m * 256 + j) = dv;
    *(float4*)(g_norm + (size_t)m * 256 + j) = nv;
    float ad = alpha_dot[0], an = alpha_norm[0];
    uint32_t* inv32 = (uint32_t*)g_invb;
    inv32[((size_t)m * 512 + j) >> 1]       = pack_bf2(ad * d0, ad * d1);
    inv32[(((size_t)m * 512 + j) >> 1) + 1] = pack_bf2(ad * d2, ad * d3);
    inv32[((size_t)m * 512 + 256 + j) >> 1]       = pack_bf2(an * n0, an * n1);
    inv32[(((size_t)m * 512 + 256 + j) >> 1) + 1] = pack_bf2(an * n2, an * n3);
}

// ---------------- flash attention v7: 4-stage cp.async ring, ONE sync/iter ----------------
// BQ=128, grid (16, 8, 4), 256 threads (8 warps); each warp: 16 q-rows x all keys.
// V row-major [key][dv], B-fragments via ldmatrix.trans. Fixed-max softmax.
// Stage = Ks 64x20 u32 (5120 B) + Vs 64x68 u32 (17408 B) = 22528 B; 4 stages = 90112 B (dynamic).
// Schedule per iter kt: wait_group<=2 (guarantees tile kt's group done: it is >=3 commits old),
// sync (publishes smem + closes iter kt-1 reads), commit ONE group (tile kt+3 or empty),
// compute stage kt&3. Tile kt+3 writes stage (kt+3)&3 != kt&3; last read iter kt-1, sync-guarded.
__global__ __launch_bounds__(256, 1) void flash7_k()
{
    extern __shared__ __align__(16) char raw[];
    const uint32_t smem_base = (uint32_t)__cvta_generic_to_shared(raw);
    uint32_t (*bufu)[66] = (uint32_t(*)[66])raw;   // writeout alias

    const int qt = blockIdx.x, h = blockIdx.y, b = blockIdx.z;
    const int tid = threadIdx.x;
    const int w = tid >> 5, lane = tid & 31;
    const int l4 = lane >> 2, lm4 = lane & 3, sel = lane >> 3;
    const int r1 = w * 16 + l4;

    uint32_t qf[2][4];
    {
        const uint32_t* qb = (const uint32_t*)g_qb;
        const uint32_t* q1 = qb + (size_t)(b * 2048 + qt * 128 + r1) * 128 + h * 16;
        const uint32_t* q2 = q1 + 8 * 128;
        qf[0][0] = q1[lm4];     qf[0][1] = q2[lm4];
        qf[0][2] = q1[lm4 + 4]; qf[0][3] = q2[lm4 + 4];
        qf[1][0] = q1[8 + lm4];     qf[1][1] = q2[8 + lm4];
        qf[1][2] = q1[8 + lm4 + 4]; qf[1][3] = q2[8 + lm4 + 4];
    }

    float l1 = 0.f, l2 = 0.f;
    float o[16][4];
#pragma unroll
    for (int nt = 0; nt < 16; nt++)
#pragma unroll
        for (int e = 0; e < 4; e++) o[nt][e] = 0.f;

    // loader geometry: thread -> key row (tid>>2), 16B segment (tid&3)
    const int krow = tid >> 2, kseg = tid & 3;
    const uint32_t* kbg = (const uint32_t*)g_kb;
    const uint32_t* vbg = (const uint32_t*)g_vb;
    const uint32_t* xbg = (const uint32_t*)g_xb;
    const uint32_t kdst0 = smem_base + (krow * 20 + kseg * 4) * 4;
    const uint32_t vdst0 = smem_base + 5120 + (krow * 68 + kseg * 16) * 4;

    auto issue_tile = [&](int kt2) {
        int tok = b * 2048 + kt2 * 64 + krow;
        uint32_t so = (uint32_t)(kt2 & 3) * 22528;
        cpa16(kdst0 + so, kbg + (size_t)tok * 128 + h * 16 + kseg * 4);
        const uint32_t* vsrc;
        if (kseg == 0) vsrc = vbg + (size_t)tok * 128 + h * 16;
        else           vsrc = xbg + (size_t)tok * 512 + 128 + (kseg - 1) * 128 + h * 16;
#pragma unroll
        for (int i = 0; i < 4; i++)
            cpa16(vdst0 + so + i * 16, vsrc + i * 4);
        cpa_commit();
    };

    // prologue: tiles 0,1,2 -> stages 0,1,2 (3 groups)
    issue_tile(0);
    issue_tile(1);
    issue_tile(2);

    for (int kt = 0; kt < 32; kt++) {
        cpa_wait<2>();
        __syncthreads();
        // exactly one commit per iteration keeps the wait<2> window valid
        if (kt + 3 < 32) issue_tile(kt + 3);
        else cpa_commit();

        const char* stage = raw + (kt & 3) * 22528;
        const char* Kst = stage;            // [64][20] u32
        const char* Vst = stage + 5120;     // [64][68] u32

        // ---- S = Q K^T : 16 rows x 64 keys ----
        float s[8][4];
#pragma unroll
        for (int nt = 0; nt < 8; nt++)
#pragma unroll
            for (int e = 0; e < 4; e++) s[nt][e] = 0.f;

#pragma unroll
        for (int ks = 0; ks < 2; ks++) {
#pragma unroll
            for (int jp = 0; jp < 4; jp++) {
                int ntE = jp * 2 + (sel >> 1);
                int rowE = ntE * 8 + (lane & 7);
                int col = ks * 8 + (sel & 1) * 4;
                uint32_t b0, b1, b2, b3;
                ldsm4(b0, b1, b2, b3, Kst + rowE * 80 + col * 4);
                mma_bf16(s[jp * 2 + 0], qf[ks][0], qf[ks][1], qf[ks][2], qf[ks][3], b0, b1);
                mma_bf16(s[jp * 2 + 1], qf[ks][0], qf[ks][1], qf[ks][2], qf[ks][3], b2, b3);
            }
        }

        // ---- p = exp(s), per-thread row sums, pack A-fragments ----
        uint32_t pa[4][4];
#pragma unroll
        for (int ks = 0; ks < 4; ks++) {
            float p00 = __expf(s[2 * ks][0]);
            float p01 = __expf(s[2 * ks][1]);
            float p02 = __expf(s[2 * ks][2]);
            float p03 = __expf(s[2 * ks][3]);
            float p10 = __expf(s[2 * ks + 1][0]);
            float p11 = __expf(s[2 * ks + 1][1]);
            float p12 = __expf(s[2 * ks + 1][2]);
            float p13 = __expf(s[2 * ks + 1][3]);
            l1 += p00 + p01 + p10 + p11;
            l2 += p02 + p03 + p12 + p13;
            pa[ks][0] = pack_bf2(p00, p01);
            pa[ks][1] = pack_bf2(p02, p03);
            pa[ks][2] = pack_bf2(p10, p11);
            pa[ks][3] = pack_bf2(p12, p13);
        }

        // ---- O += P V : B-fragments via ldsm.trans from row-major V ----
#pragma unroll
        for (int ks = 0; ks < 4; ks++) {
#pragma unroll
            for (int jj = 0; jj < 8; jj++) {
                int vrow = ks * 16 + (sel & 1) * 8 + (lane & 7);
                int vcol = jj * 8 + (sel >> 1) * 4;
                uint32_t b0, b1, b2, b3;
                ldsm4t(b0, b1, b2, b3, Vst + vrow * 272 + vcol * 4);
                mma_bf16(o[2 * jj + 0], pa[ks][0], pa[ks][1], pa[ks][2], pa[ks][3], b0, b1);
                mma_bf16(o[2 * jj + 1], pa[ks][0], pa[ks][1], pa[ks][2], pa[ks][3], b2, b3);
            }
        }
    }

    // ---- row-sum reduce (warp-local) ----
    l1 += __shfl_xor_sync(0xffffffffu, l1, 1);
    l1 += __shfl_xor_sync(0xffffffffu, l1, 2);
    l2 += __shfl_xor_sync(0xffffffffu, l2, 1);
    l2 += __shfl_xor_sync(0xffffffffu, l2, 2);
    float w1 = 1.f / l1, w2 = 1.f / l2;

    // ---- two-phase staged writeout through smem ----
#pragma unroll
    for (int ph = 0; ph < 2; ph++) {
        __syncthreads();
        if ((w >> 2) == ph) {
            int lr1 = (w & 3) * 16 + l4, lr2 = lr1 + 8;
#pragma unroll
            for (int nt = 0; nt < 16; nt++) {
                bufu[lr1][nt * 4 + lm4] = pack_bf2(o[nt][0] * w1, o[nt][1] * w1);
                bufu[lr2][nt * 4 + lm4] = pack_bf2(o[nt][2] * w2, o[nt][3] * w2);
            }
        }
        __syncthreads();
        int r = tid >> 2, qtr = tid & 3;
        int tok = b * 2048 + qt * 128 + ph * 64 + r;
        if (qtr == 0) {
            uint32_t* dst = (uint32_t*)g_xoutb + (size_t)tok * 128 + h * 16;
#pragma unroll
            for (int i = 0; i < 16; i++)
                dst[i] = bufu[r][i];
        } else {
            int c = qtr - 1;
            uint32_t* dst = (uint32_t*)g_vaggrb + (((size_t)tok * 768 + c * 256 + h * 32) >> 1);
#pragma unroll
            for (int i = 0; i < 16; i++)
                dst[i] = bufu[r][qtr * 16 + i];
        }
    }
}

// ---------------- final elementwise combine ----------------
__global__ __launch_bounds__(256) void final_k(const float* __restrict__ x, float* __restrict__ out)
{
    int idx = blockIdx.x * blockDim.x + threadIdx.x;
    if (idx >= 8192 * 64) return;
    int m = idx >> 6, j = (idx & 63) << 2;

    const uint32_t* ob = (const uint32_t*)g_ob;
    size_t base = (size_t)m * 768;
    uint32_t u;
    u = ob[(base + j) >> 1];       float2 o1a = unpack_bf2(u);
    u = ob[((base + j) >> 1) + 1]; float2 o1b = unpack_bf2(u);
    u = ob[(base + 256 + j) >> 1];       float2 o2a = unpack_bf2(u);
    u = ob[((base + 256 + j) >> 1) + 1]; float2 o2b = unpack_bf2(u);
    u = ob[(base + 512 + j) >> 1];       float2 o3a = unpack_bf2(u);
    u = ob[((base + 512 + j) >> 1) + 1]; float2 o3b = unpack_bf2(u);

    float4 vd = *(const float4*)(g_dot + (size_t)m * 256 + j);
    float4 vn = *(const float4*)(g_norm + (size_t)m * 256 + j);
    float4 r;
    r.x = vd.x * o1a.x + vn.x * o2a.x + o3a.x;
    r.y = vd.y * o1a.y + vn.y * o2a.y + o3a.y;
    r.z = vd.z * o1b.x + vn.z * o2b.x + o3b.x;
    r.w = vd.w * o1b.y + vn.w * o2b.y + o3b.y;
    *(float4*)(out + (size_t)m * 1024 + j) = r;

    const uint32_t* gb = (const uint32_t*)g_gateb;
    u = gb[((size_t)m * 256 + j) >> 1];       float2 ga = unpack_bf2(u);
    u = gb[(((size_t)m * 256 + j) >> 1) + 1]; float2 gbv = unpack_bf2(u);
    const uint32_t* vab = (const uint32_t*)g_vaggrb;
#pragma unroll
    for (int c = 0; c < 3; c++) {
        size_t xi = (size_t)m * 1024 + 256 + c * 256 + j;
        u = vab[(base + c * 256 + j) >> 1];       float2 va = unpack_bf2(u);
        u = vab[((base + c * 256 + j) >> 1) + 1]; float2 vb = unpack_bf2(u);
        float4 xv = *(const float4*)(x + xi);
        float4 rr;
        rr.x = ga.x * va.x + xv.x;
        rr.y = ga.y * va.y + xv.y;
        rr.z = gbv.x * vb.x + xv.z;
        rr.w = gbv.y * vb.y + xv.w;
        *(float4*)(out + xi) = rr;
    }
}

// ---------------- launch ----------------
extern "C" void kernel_launch(void* const* d_in, const int* in_sizes, int n_in,
                              void* d_out, int out_size)
{
    const float* x    = (const float*)d_in[0];
    const float* Wq   = (const float*)d_in[1];
    const float* bq   = (const float*)d_in[2];
    const float* Wk   = (const float*)d_in[3];
    const float* bk   = (const float*)d_in[4];
    const float* Wv   = (const float*)d_in[5];
    const float* bv   = (const float*)d_in[6];
    const float* Wvec = (const float*)d_in[7];
    const float* Wo   = (const float*)d_in[8];
    const float* bo   = (const float*)d_in[9];
    const float* Wg   = (const float*)d_in[10];
    const float* bg   = (const float*)d_in[11];
    const float* adot = (const float*)d_in[12];
    const float* anrm = (const float*)d_in[13];
    float* out = (float*)d_out;

    void *xbp, *wqkvp, *bqkvp, *wvecp, *wgp, *wop;
    void *qbp, *kbp, *vbp, *projbp, *invbp, *xoutbp, *gatep, *obp;
    cudaGetSymbolAddress(&xbp, g_xb);
    cudaGetSymbolAddress(&wqkvp, g_wqkv);
    cudaGetSymbolAddress(&bqkvp, g_bqkv);
    cudaGetSymbolAddress(&wvecp, g_wvecb);
    cudaGetSymbolAddress(&wgp, g_wgb);
    cudaGetSymbolAddress(&wop, g_wob);
    cudaGetSymbolAddress(&qbp, g_qb);
    cudaGetSymbolAddress(&kbp, g_kb);
    cudaGetSymbolAddress(&vbp, g_vb);
    cudaGetSymbolAddress(&projbp, g_projb);
    cudaGetSymbolAddress(&invbp, g_invb);
    cudaGetSymbolAddress(&xoutbp, g_xoutb);
    cudaGetSymbolAddress(&gatep, g_gateb);
    cudaGetSymbolAddress(&obp, g_ob);

    static bool attr_set = false;
    if (!attr_set) {
        cudaFuncSetAttribute(flash7_k, cudaFuncAttributeMaxDynamicSharedMemorySize, 90112);
        attr_set = true;
    }

    dim3 blk(256);
    prep_all_k<<<8833, blk>>>(x, Wq, Wk, Wv, Wvec, Wg, Wo, bq, bk, bv);
    // fused q/k/v: M=8192, N=768, K=256
    gemm3_k<0, 4><<<dim3(6, 64), blk>>>(
        (const __nv_bfloat16*)xbp, (const __nv_bfloat16*)wqkvp, (const float*)bqkvp,
        qbp, kbp, vbp, 256, 1024, 256);
    // vec proj: M=24576, N=512, K=256
    gemm3_k<1, 1><<<dim3(4, 192), blk>>>(
        (const __nv_bfloat16*)xbp, (const __nv_bfloat16*)wvecp, nullptr,
        projbp, nullptr, nullptr, 256, 0, 512);
    // invariants
    inv_k<<<2048, blk>>>(adot, anrm);
    // gate: M=8192, N=256, K=512, sigmoid bf16 out
    gemm3_k<0, 5><<<dim3(2, 64), blk>>>(
        (const __nv_bfloat16*)invbp, (const __nv_bfloat16*)wgp, bg,
        gatep, nullptr, nullptr, 512, 512, 256);
    flash7_k<<<dim3(16, 8, 4), blk, 90112>>>();
    // Wo: M=8192, N=768, K=256, bf16 out
    gemm3_k<0, 1><<<dim3(6, 64), blk>>>(
        (const __nv_bfloat16*)xoutbp, (const __nv_bfloat16*)wop, bo,
        obp, nullptr, nullptr, 256, 256, 768);
    final_k<<<2048, blk>>>(x, out);
}

// round 13
// speedup vs baseline: 1.2506x; 1.0681x over previous
#include <cuda_runtime.h>
#include <cuda_bf16.h>
#include <math.h>
#include <stdint.h>

// ---------------- scratch (static device memory; no allocations) ----------------
__device__ __nv_bfloat16 g_xb[8192 * 1024];
__device__ __nv_bfloat16 g_wqkv[768 * 256];
__device__ float         g_bqkv[768];
__device__ __nv_bfloat16 g_wvecb[512 * 256];
__device__ __nv_bfloat16 g_wgb[256 * 512];
__device__ __nv_bfloat16 g_wob[768 * 256];
__device__ __nv_bfloat16 g_qb[8192 * 256];
__device__ __nv_bfloat16 g_kb[8192 * 256];
__device__ __nv_bfloat16 g_vb[8192 * 256];
__device__ __nv_bfloat16 g_projb[24576 * 512];
__device__ __nv_bfloat16 g_invb[8192 * 512];
__device__ __nv_bfloat16 g_xoutb[8192 * 256];
__device__ __nv_bfloat16 g_dotb[8192 * 256];
__device__ __nv_bfloat16 g_normb[8192 * 256];
__device__ __nv_bfloat16 g_gateb[8192 * 256];
__device__ __nv_bfloat16 g_vaggrb[8192 * 768];
__device__ __nv_bfloat16 g_ob[8192 * 768];

// ---------------- helpers ----------------
__device__ __forceinline__ uint32_t pack_bf2(float lo, float hi) {
    uint32_t r;
    asm("cvt.rn.bf16x2.f32 %0, %1, %2;" : "=r"(r) : "f"(hi), "f"(lo));
    return r;
}
__device__ __forceinline__ float2 unpack_bf2(uint32_t u) {
    __nv_bfloat162 h = *reinterpret_cast<__nv_bfloat162*>(&u);
    return __bfloat1622float2(h);
}
__device__ __forceinline__ void mma_bf16(float* c,
    uint32_t a0, uint32_t a1, uint32_t a2, uint32_t a3,
    uint32_t b0, uint32_t b1)
{
    asm volatile("mma.sync.aligned.m16n8k16.row.col.f32.bf16.bf16.f32 "
        "{%0,%1,%2,%3}, {%4,%5,%6,%7}, {%8,%9}, {%0,%1,%2,%3};"
        : "+f"(c[0]), "+f"(c[1]), "+f"(c[2]), "+f"(c[3])
        : "r"(a0), "r"(a1), "r"(a2), "r"(a3), "r"(b0), "r"(b1));
}
__device__ __forceinline__ void ldsm4(uint32_t& r0, uint32_t& r1, uint32_t& r2, uint32_t& r3,
                                      const void* p)
{
    uint32_t a = (uint32_t)__cvta_generic_to_shared(p);
    asm volatile("ldmatrix.sync.aligned.m8n8.x4.shared.b16 {%0,%1,%2,%3}, [%4];"
        : "=r"(r0), "=r"(r1), "=r"(r2), "=r"(r3) : "r"(a));
}
__device__ __forceinline__ void ldsm4t(uint32_t& r0, uint32_t& r1, uint32_t& r2, uint32_t& r3,
                                       const void* p)
{
    uint32_t a = (uint32_t)__cvta_generic_to_shared(p);
    asm volatile("ldmatrix.sync.aligned.m8n8.x4.trans.shared.b16 {%0,%1,%2,%3}, [%4];"
        : "=r"(r0), "=r"(r1), "=r"(r2), "=r"(r3) : "r"(a));
}
__device__ __forceinline__ void cpa16(uint32_t dst, const void* src) {
    asm volatile("cp.async.cg.shared.global [%0], [%1], 16;" :: "r"(dst), "l"(src));
}
__device__ __forceinline__ void cpa_commit() {
    asm volatile("cp.async.commit_group;");
}
template <int N>
__device__ __forceinline__ void cpa_wait() {
    asm volatile("cp.async.wait_group %0;" :: "n"(N));
}

// ---------------- fused prep: x -> bf16, weights -> bf16 (32B/thread) ----------------
__device__ __forceinline__ void cvt4(__nv_bfloat16* dst, const float* src) {
    float4 f = *(const float4*)src;
    uint32_t* d = (uint32_t*)dst;
    d[0] = pack_bf2(f.x, f.y);
    d[1] = pack_bf2(f.z, f.w);
}
__device__ __forceinline__ void cvt8(__nv_bfloat16* dst, const float* src) {
    cvt4(dst, src);
    cvt4(dst + 4, src + 4);
}
__global__ __launch_bounds__(256) void prep_all_k(
    const float* __restrict__ x,
    const float* __restrict__ Wq, const float* __restrict__ Wk, const float* __restrict__ Wv,
    const float* __restrict__ Wvec, const float* __restrict__ Wg, const float* __restrict__ Wo,
    const float* __restrict__ bq, const float* __restrict__ bk, const float* __restrict__ bv)
{
    int bid = blockIdx.x;
    if (bid < 4096) {
        // x: 2 rows per block, 8 elems per thread
        size_t base = (size_t)bid * 2048 + threadIdx.x * 8;
        cvt8(g_xb + base, x + base);
        return;
    }
    long i = (long)((bid - 4096) * 256 + threadIdx.x) << 3;
    if (i < 65536)        cvt8(g_wqkv + i, Wq + i);
    else if (i < 131072)  cvt8(g_wqkv + i, Wk + (i - 65536));
    else if (i < 196608)  cvt8(g_wqkv + i, Wv + (i - 131072));
    else if (i < 327680)  cvt8(g_wvecb + (i - 196608), Wvec + (i - 196608));
    else if (i < 458752)  cvt8(g_wgb + (i - 327680), Wg + (i - 327680));
    else if (i < 655360)  cvt8(g_wob + (i - 458752), Wo + (i - 458752));
    else if (i < 656128) {
        int j = (int)(i - 655360);
        // biases stay fp32: 8 floats per thread
        const float* src;
        float* dst = g_bqkv + j;
        if (j < 256)      src = bq + j;
        else if (j < 512) src = bk + (j - 256);
        else              src = bv + (j - 512);
        *(float4*)dst = *(const float4*)src;
        *(float4*)(dst + 4) = *(const float4*)(src + 4);
    }
}

// ---------------- bf16 cp.async GEMM body (inlined into fused kernels) ----------------
// BM=128, BN=128, BK=32; 256 threads = 8 warps (2 m x 4 n), warp tile 64x32.
// ROWMAP 0: A row = Ab + (bm+r)*lda.  ROWMAP 1: vec rows of g_xb.
// OUT: 1 bf16; 4 qkv-split; 5 sigmoid bf16.
template <int ROWMAP, int OUT>
__device__ __forceinline__ void gemm_body(
    uint32_t (*SA)[128][20], uint32_t (*SB)[128][20],
    int bn_blk, int bm_blk,
    const __nv_bfloat16* __restrict__ Ab, const __nv_bfloat16* __restrict__ Wb,
    const float* __restrict__ bias, void* __restrict__ Cv,
    void* __restrict__ Cv2, void* __restrict__ Cv3,
    int K, int lda, int ldc)
{
    const int tid = threadIdx.x;
    const int w = tid >> 5, lane = tid & 31;
    const int l4 = lane >> 2, lm4 = lane & 3, sel = lane >> 3;
    const int wr = w >> 2, wc = w & 3;
    const int bm = bm_blk << 7, bn = bn_blk << 7;

    const int r0 = tid >> 2, off = tid & 3;
    const __nv_bfloat16 *pa0, *pa1;
    if (ROWMAP == 0) {
        pa0 = Ab + (size_t)(bm + r0) * lda + off * 8;
        pa1 = Ab + (size_t)(bm + r0 + 64) * lda + off * 8;
    } else {
        int g0 = bm + r0, m0 = g0 / 3, c0 = g0 - 3 * m0;
        int g1 = bm + r0 + 64, m1 = g1 / 3, c1 = g1 - 3 * m1;
        pa0 = Ab + (size_t)m0 * 1024 + (size_t)(c0 + 1) * 256 + off * 8;
        pa1 = Ab + (size_t)m1 * 1024 + (size_t)(c1 + 1) * 256 + off * 8;
    }
    const __nv_bfloat16* pb0 = Wb + (size_t)(bn + r0) * K + off * 8;
    const __nv_bfloat16* pb1 = Wb + (size_t)(bn + r0 + 64) * K + off * 8;

    const uint32_t saA = (uint32_t)__cvta_generic_to_shared(&SA[0][0][0]);
    const uint32_t saB = (uint32_t)__cvta_generic_to_shared(&SB[0][0][0]);
    const uint32_t dA0 = saA + (r0 * 20 + off * 4) * 4;
    const uint32_t dA1 = saA + ((r0 + 64) * 20 + off * 4) * 4;
    const uint32_t dB0 = saB + (r0 * 20 + off * 4) * 4;
    const uint32_t dB1 = saB + ((r0 + 64) * 20 + off * 4) * 4;
    const uint32_t stB = 2560 * 4;

    float acc[4][4][4];
#pragma unroll
    for (int mt = 0; mt < 4; mt++)
#pragma unroll
        for (int nt = 0; nt < 4; nt++)
#pragma unroll
            for (int e = 0; e < 4; e++) acc[mt][nt][e] = 0.f;

    const int niter = K >> 5;

#pragma unroll
    for (int st = 0; st < 2; st++) {
        int k0 = st << 5;
        cpa16(dA0 + st * stB, pa0 + k0);
        cpa16(dA1 + st * stB, pa1 + k0);
        cpa16(dB0 + st * stB, pb0 + k0);
        cpa16(dB1 + st * stB, pb1 + k0);
        cpa_commit();
    }

    for (int it = 0; it < niter; it++) {
        if (it + 1 < niter) cpa_wait<1>(); else cpa_wait<0>();
        __syncthreads();
        const int st = it & 1;

#pragma unroll
        for (int ks = 0; ks < 2; ks++) {
            uint32_t af[4][4];
#pragma unroll
            for (int mt = 0; mt < 4; mt++)
                ldsm4(af[mt][0], af[mt][1], af[mt][2], af[mt][3],
                      &SA[st][wr * 64 + mt * 16 + (lane & 15)][ks * 8 + (lane >> 4) * 4]);
            uint32_t bf[4][2];
#pragma unroll
            for (int jp = 0; jp < 2; jp++) {
                uint32_t b0, b1, b2, b3;
                ldsm4(b0, b1, b2, b3,
                      &SB[st][wc * 32 + (jp * 2 + (sel >> 1)) * 8 + (lane & 7)][ks * 8 + (sel & 1) * 4]);
                bf[jp * 2][0] = b0; bf[jp * 2][1] = b1;
                bf[jp * 2 + 1][0] = b2; bf[jp * 2 + 1][1] = b3;
            }
#pragma unroll
            for (int mt = 0; mt < 4; mt++)
#pragma unroll
                for (int nt = 0; nt < 4; nt++)
                    mma_bf16(acc[mt][nt], af[mt][0], af[mt][1], af[mt][2], af[mt][3],
                             bf[nt][0], bf[nt][1]);
        }
        __syncthreads();
        if (it + 2 < niter) {
            int k0 = (it + 2) << 5;
            cpa16(dA0 + st * stB, pa0 + k0);
            cpa16(dA1 + st * stB, pa1 + k0);
            cpa16(dB0 + st * stB, pb0 + k0);
            cpa16(dB1 + st * stB, pb1 + k0);
            cpa_commit();
        }
    }

    const float qscale = 0.17677669529663687f;
#pragma unroll
    for (int mt = 0; mt < 4; mt++) {
#pragma unroll
        for (int nt = 0; nt < 4; nt++) {
            int c = bn + wc * 32 + nt * 8 + lm4 * 2;
            float bx = 0.f, by = 0.f;
            if (bias) { bx = bias[c]; by = bias[c + 1]; }
#pragma unroll
            for (int half = 0; half < 2; half++) {
                int r = bm + wr * 64 + mt * 16 + l4 + half * 8;
                float vx = acc[mt][nt][half * 2 + 0] + bx;
                float vy = acc[mt][nt][half * 2 + 1] + by;
                if (OUT == 5) {
                    vx = 1.f / (1.f + __expf(-vx));
                    vy = 1.f / (1.f + __expf(-vy));
                    ((uint32_t*)Cv)[((size_t)r * ldc + c) >> 1] = pack_bf2(vx, vy);
                } else if (OUT == 1) {
                    ((uint32_t*)Cv)[((size_t)r * ldc + c) >> 1] = pack_bf2(vx, vy);
                } else {  // OUT == 4: qkv split
                    int third = c >> 8, lc = c & 255;
                    void* dst = (third == 0) ? Cv : (third == 1 ? Cv2 : Cv3);
                    if (third == 0) { vx *= qscale; vy *= qscale; }
                    ((uint32_t*)dst)[((size_t)r * 256 + lc) >> 1] = pack_bf2(vx, vy);
                }
            }
        }
    }
}

// ---------------- fused GEMM launch 1: qkv (384 blocks) + vec-proj (768 blocks) ----------------
__global__ __launch_bounds__(256, 2) void gemm_qkvvec_k(
    const __nv_bfloat16* __restrict__ xb, const __nv_bfloat16* __restrict__ wqkv,
    const float* __restrict__ bqkv, const __nv_bfloat16* __restrict__ wvec,
    void* qb, void* kbv, void* vb, void* projb)
{
    __shared__ uint32_t SA[2][128][20];
    __shared__ uint32_t SB[2][128][20];
    int bid = blockIdx.x;
    if (bid < 384) {
        gemm_body<0, 4>(SA, SB, bid % 6, bid / 6, xb, wqkv, bqkv,
                        qb, kbv, vb, 256, 1024, 256);
    } else {
        int b2 = bid - 384;
        gemm_body<1, 1>(SA, SB, b2 % 4, b2 / 4, xb, wvec, nullptr,
                        projb, nullptr, nullptr, 256, 0, 512);
    }
}

// ---------------- fused GEMM launch 2: Wo (384 blocks) + gate (128 blocks) ----------------
__global__ __launch_bounds__(256, 2) void gemm_ogate_k(
    const __nv_bfloat16* __restrict__ xoutb, const __nv_bfloat16* __restrict__ wob,
    const float* __restrict__ bo, const __nv_bfloat16* __restrict__ invb,
    const __nv_bfloat16* __restrict__ wgb, const float* __restrict__ bg,
    void* ob, void* gateb)
{
    __shared__ uint32_t SA[2][128][20];
    __shared__ uint32_t SB[2][128][20];
    int bid = blockIdx.x;
    if (bid < 384) {
        gemm_body<0, 1>(SA, SB, bid % 6, bid / 6, xoutb, wob, bo,
                        ob, nullptr, nullptr, 256, 256, 768);
    } else {
        int b2 = bid - 384;
        gemm_body<0, 5>(SA, SB, b2 % 2, b2 / 2, invb, wgb, bg,
                        gateb, nullptr, nullptr, 512, 512, 256);
    }
}

// ---------------- invariants (dot/norm stored bf16) ----------------
__global__ __launch_bounds__(256) void inv_k(
    const float* __restrict__ alpha_dot, const float* __restrict__ alpha_norm)
{
    int idx = blockIdx.x * 256 + threadIdx.x;
    int m = idx >> 6, j = (idx & 63) << 2;
    const uint32_t* xb32 = (const uint32_t*)g_xb;
    float d0 = 0.f, d1 = 0.f, d2 = 0.f, d3 = 0.f;
    float n0 = 0.f, n1 = 0.f, n2 = 0.f, n3 = 0.f;
#pragma unroll
    for (int c = 0; c < 3; c++) {
        const uint32_t* pr = (const uint32_t*)(g_projb + (size_t)(m * 3 + c) * 512);
        uint32_t a0 = pr[(j >> 1)], a1 = pr[(j >> 1) + 1];
        uint32_t b0 = pr[128 + (j >> 1)], b1 = pr[129 + (j >> 1)];
        float2 fa0 = unpack_bf2(a0), fa1 = unpack_bf2(a1);
        float2 fb0 = unpack_bf2(b0), fb1 = unpack_bf2(b1);
        d0 += fa0.x * fb0.x; d1 += fa0.y * fb0.y;
        d2 += fa1.x * fb1.x; d3 += fa1.y * fb1.y;
        uint32_t x0 = xb32[((size_t)m * 1024 + 256 + c * 256 + j) >> 1];
        uint32_t x1 = xb32[(((size_t)m * 1024 + 256 + c * 256 + j) >> 1) + 1];
        float2 fx0 = unpack_bf2(x0), fx1 = unpack_bf2(x1);
        n0 += fx0.x * fx0.x; n1 += fx0.y * fx0.y;
        n2 += fx1.x * fx1.x; n3 += fx1.y * fx1.y;
    }
    n0 = sqrtf(n0); n1 = sqrtf(n1); n2 = sqrtf(n2); n3 = sqrtf(n3);
    uint32_t* db = (uint32_t*)g_dotb;
    uint32_t* nb = (uint32_t*)g_normb;
    size_t o4 = ((size_t)m * 256 + j) >> 1;
    db[o4]     = pack_bf2(d0, d1);
    db[o4 + 1] = pack_bf2(d2, d3);
    nb[o4]     = pack_bf2(n0, n1);
    nb[o4 + 1] = pack_bf2(n2, n3);
    float ad = alpha_dot[0], an = alpha_norm[0];
    uint32_t* inv32 = (uint32_t*)g_invb;
    inv32[((size_t)m * 512 + j) >> 1]       = pack_bf2(ad * d0, ad * d1);
    inv32[(((size_t)m * 512 + j) >> 1) + 1] = pack_bf2(ad * d2, ad * d3);
    inv32[((size_t)m * 512 + 256 + j) >> 1]       = pack_bf2(an * n0, an * n1);
    inv32[(((size_t)m * 512 + 256 + j) >> 1) + 1] = pack_bf2(an * n2, an * n3);
}

// ---------------- flash attention v7: 4-stage cp.async ring, ONE sync/iter ----------------
__global__ __launch_bounds__(256, 1) void flash7_k()
{
    extern __shared__ __align__(16) char raw[];
    const uint32_t smem_base = (uint32_t)__cvta_generic_to_shared(raw);
    uint32_t (*bufu)[66] = (uint32_t(*)[66])raw;

    const int qt = blockIdx.x, h = blockIdx.y, b = blockIdx.z;
    const int tid = threadIdx.x;
    const int w = tid >> 5, lane = tid & 31;
    const int l4 = lane >> 2, lm4 = lane & 3, sel = lane >> 3;
    const int r1 = w * 16 + l4;

    uint32_t qf[2][4];
    {
        const uint32_t* qb = (const uint32_t*)g_qb;
        const uint32_t* q1 = qb + (size_t)(b * 2048 + qt * 128 + r1) * 128 + h * 16;
        const uint32_t* q2 = q1 + 8 * 128;
        qf[0][0] = q1[lm4];     qf[0][1] = q2[lm4];
        qf[0][2] = q1[lm4 + 4]; qf[0][3] = q2[lm4 + 4];
        qf[1][0] = q1[8 + lm4];     qf[1][1] = q2[8 + lm4];
        qf[1][2] = q1[8 + lm4 + 4]; qf[1][3] = q2[8 + lm4 + 4];
    }

    float l1 = 0.f, l2 = 0.f;
    float o[16][4];
#pragma unroll
    for (int nt = 0; nt < 16; nt++)
#pragma unroll
        for (int e = 0; e < 4; e++) o[nt][e] = 0.f;

    const int krow = tid >> 2, kseg = tid & 3;
    const uint32_t* kbg = (const uint32_t*)g_kb;
    const uint32_t* vbg = (const uint32_t*)g_vb;
    const uint32_t* xbg = (const uint32_t*)g_xb;
    const uint32_t kdst0 = smem_base + (krow * 20 + kseg * 4) * 4;
    const uint32_t vdst0 = smem_base + 5120 + (krow * 68 + kseg * 16) * 4;

    auto issue_tile = [&](int kt2) {
        int tok = b * 2048 + kt2 * 64 + krow;
        uint32_t so = (uint32_t)(kt2 & 3) * 22528;
        cpa16(kdst0 + so, kbg + (size_t)tok * 128 + h * 16 + kseg * 4);
        const uint32_t* vsrc;
        if (kseg == 0) vsrc = vbg + (size_t)tok * 128 + h * 16;
        else           vsrc = xbg + (size_t)tok * 512 + 128 + (kseg - 1) * 128 + h * 16;
#pragma unroll
        for (int i = 0; i < 4; i++)
            cpa16(vdst0 + so + i * 16, vsrc + i * 4);
        cpa_commit();
    };

    issue_tile(0);
    issue_tile(1);
    issue_tile(2);

    for (int kt = 0; kt < 32; kt++) {
        cpa_wait<2>();
        __syncthreads();
        if (kt + 3 < 32) issue_tile(kt + 3);
        else cpa_commit();

        const char* stage = raw + (kt & 3) * 22528;
        const char* Kst = stage;
        const char* Vst = stage + 5120;

        float s[8][4];
#pragma unroll
        for (int nt = 0; nt < 8; nt++)
#pragma unroll
            for (int e = 0; e < 4; e++) s[nt][e] = 0.f;

#pragma unroll
        for (int ks = 0; ks < 2; ks++) {
#pragma unroll
            for (int jp = 0; jp < 4; jp++) {
                int ntE = jp * 2 + (sel >> 1);
                int rowE = ntE * 8 + (lane & 7);
                int col = ks * 8 + (sel & 1) * 4;
                uint32_t b0, b1, b2, b3;
                ldsm4(b0, b1, b2, b3, Kst + rowE * 80 + col * 4);
                mma_bf16(s[jp * 2 + 0], qf[ks][0], qf[ks][1], qf[ks][2], qf[ks][3], b0, b1);
                mma_bf16(s[jp * 2 + 1], qf[ks][0], qf[ks][1], qf[ks][2], qf[ks][3], b2, b3);
            }
        }

        uint32_t pa[4][4];
#pragma unroll
        for (int ks = 0; ks < 4; ks++) {
            float p00 = __expf(s[2 * ks][0]);
            float p01 = __expf(s[2 * ks][1]);
            float p02 = __expf(s[2 * ks][2]);
            float p03 = __expf(s[2 * ks][3]);
            float p10 = __expf(s[2 * ks + 1][0]);
            float p11 = __expf(s[2 * ks + 1][1]);
            float p12 = __expf(s[2 * ks + 1][2]);
            float p13 = __expf(s[2 * ks + 1][3]);
            l1 += p00 + p01 + p10 + p11;
            l2 += p02 + p03 + p12 + p13;
            pa[ks][0] = pack_bf2(p00, p01);
            pa[ks][1] = pack_bf2(p02, p03);
            pa[ks][2] = pack_bf2(p10, p11);
            pa[ks][3] = pack_bf2(p12, p13);
        }

#pragma unroll
        for (int ks = 0; ks < 4; ks++) {
#pragma unroll
            for (int jj = 0; jj < 8; jj++) {
                int vrow = ks * 16 + (sel & 1) * 8 + (lane & 7);
                int vcol = jj * 8 + (sel >> 1) * 4;
                uint32_t b0, b1, b2, b3;
                ldsm4t(b0, b1, b2, b3, Vst + vrow * 272 + vcol * 4);
                mma_bf16(o[2 * jj + 0], pa[ks][0], pa[ks][1], pa[ks][2], pa[ks][3], b0, b1);
                mma_bf16(o[2 * jj + 1], pa[ks][0], pa[ks][1], pa[ks][2], pa[ks][3], b2, b3);
            }
        }
    }

    l1 += __shfl_xor_sync(0xffffffffu, l1, 1);
    l1 += __shfl_xor_sync(0xffffffffu, l1, 2);
    l2 += __shfl_xor_sync(0xffffffffu, l2, 1);
    l2 += __shfl_xor_sync(0xffffffffu, l2, 2);
    float w1 = 1.f / l1, w2 = 1.f / l2;

#pragma unroll
    for (int ph = 0; ph < 2; ph++) {
        __syncthreads();
        if ((w >> 2) == ph) {
            int lr1 = (w & 3) * 16 + l4, lr2 = lr1 + 8;
#pragma unroll
            for (int nt = 0; nt < 16; nt++) {
                bufu[lr1][nt * 4 + lm4] = pack_bf2(o[nt][0] * w1, o[nt][1] * w1);
                bufu[lr2][nt * 4 + lm4] = pack_bf2(o[nt][2] * w2, o[nt][3] * w2);
            }
        }
        __syncthreads();
        int r = tid >> 2, qtr = tid & 3;
        int tok = b * 2048 + qt * 128 + ph * 64 + r;
        if (qtr == 0) {
            uint32_t* dst = (uint32_t*)g_xoutb + (size_t)tok * 128 + h * 16;
#pragma unroll
            for (int i = 0; i < 16; i++)
                dst[i] = bufu[r][i];
        } else {
            int c = qtr - 1;
            uint32_t* dst = (uint32_t*)g_vaggrb + (((size_t)tok * 768 + c * 256 + h * 32) >> 1);
#pragma unroll
            for (int i = 0; i < 16; i++)
                dst[i] = bufu[r][qtr * 16 + i];
        }
    }
}

// ---------------- final elementwise combine ----------------
__global__ __launch_bounds__(256) void final_k(const float* __restrict__ x, float* __restrict__ out)
{
    int idx = blockIdx.x * blockDim.x + threadIdx.x;
    if (idx >= 8192 * 64) return;
    int m = idx >> 6, j = (idx & 63) << 2;

    const uint32_t* ob = (const uint32_t*)g_ob;
    size_t base = (size_t)m * 768;
    uint32_t u;
    u = ob[(base + j) >> 1];       float2 o1a = unpack_bf2(u);
    u = ob[((base + j) >> 1) + 1]; float2 o1b = unpack_bf2(u);
    u = ob[(base + 256 + j) >> 1];       float2 o2a = unpack_bf2(u);
    u = ob[((base + 256 + j) >> 1) + 1]; float2 o2b = unpack_bf2(u);
    u = ob[(base + 512 + j) >> 1];       float2 o3a = unpack_bf2(u);
    u = ob[((base + 512 + j) >> 1) + 1]; float2 o3b = unpack_bf2(u);

    const uint32_t* db = (const uint32_t*)g_dotb;
    const uint32_t* nb = (const uint32_t*)g_normb;
    size_t o4 = ((size_t)m * 256 + j) >> 1;
    float2 vda = unpack_bf2(db[o4]), vdb = unpack_bf2(db[o4 + 1]);
    float2 vna = unpack_bf2(nb[o4]), vnb = unpack_bf2(nb[o4 + 1]);

    float4 r;
    r.x = vda.x * o1a.x + vna.x * o2a.x + o3a.x;
    r.y = vda.y * o1a.y + vna.y * o2a.y + o3a.y;
    r.z = vdb.x * o1b.x + vnb.x * o2b.x + o3b.x;
    r.w = vdb.y * o1b.y + vnb.y * o2b.y + o3b.y;
    *(float4*)(out + (size_t)m * 1024 + j) = r;

    const uint32_t* gb = (const uint32_t*)g_gateb;
    u = gb[o4];     float2 ga = unpack_bf2(u);
    u = gb[o4 + 1]; float2 gbv = unpack_bf2(u);
    const uint32_t* vab = (const uint32_t*)g_vaggrb;
#pragma unroll
    for (int c = 0; c < 3; c++) {
        size_t xi = (size_t)m * 1024 + 256 + c * 256 + j;
        u = vab[(base + c * 256 + j) >> 1];       float2 va = unpack_bf2(u);
        u = vab[((base + c * 256 + j) >> 1) + 1]; float2 vb = unpack_bf2(u);
        float4 xv = *(const float4*)(x + xi);
        float4 rr;
        rr.x = ga.x * va.x + xv.x;
        rr.y = ga.y * va.y + xv.y;
        rr.z = gbv.x * vb.x + xv.z;
        rr.w = gbv.y * vb.y + xv.w;
        *(float4*)(out + xi) = rr;
    }
}

// ---------------- launch ----------------
extern "C" void kernel_launch(void* const* d_in, const int* in_sizes, int n_in,
                              void* d_out, int out_size)
{
    const float* x    = (const float*)d_in[0];
    const float* Wq   = (const float*)d_in[1];
    const float* bq   = (const float*)d_in[2];
    const float* Wk   = (const float*)d_in[3];
    const float* bk   = (const float*)d_in[4];
    const float* Wv   = (const float*)d_in[5];
    const float* bv   = (const float*)d_in[6];
    const float* Wvec = (const float*)d_in[7];
    const float* Wo   = (const float*)d_in[8];
    const float* bo   = (const float*)d_in[9];
    const float* Wg   = (const float*)d_in[10];
    const float* bg   = (const float*)d_in[11];
    const float* adot = (const float*)d_in[12];
    const float* anrm = (const float*)d_in[13];
    float* out = (float*)d_out;

    void *xbp, *wqkvp, *bqkvp, *wvecp, *wgp, *wop;
    void *qbp, *kbp, *vbp, *projbp, *invbp, *xoutbp, *gatep, *obp;
    cudaGetSymbolAddress(&xbp, g_xb);
    cudaGetSymbolAddress(&wqkvp, g_wqkv);
    cudaGetSymbolAddress(&bqkvp, g_bqkv);
    cudaGetSymbolAddress(&wvecp, g_wvecb);
    cudaGetSymbolAddress(&wgp, g_wgb);
    cudaGetSymbolAddress(&wop, g_wob);
    cudaGetSymbolAddress(&qbp, g_qb);
    cudaGetSymbolAddress(&kbp, g_kb);
    cudaGetSymbolAddress(&vbp, g_vb);
    cudaGetSymbolAddress(&projbp, g_projb);
    cudaGetSymbolAddress(&invbp, g_invb);
    cudaGetSymbolAddress(&xoutbp, g_xoutb);
    cudaGetSymbolAddress(&gatep, g_gateb);
    cudaGetSymbolAddress(&obp, g_ob);

    static bool attr_set = false;
    if (!attr_set) {
        cudaFuncSetAttribute(flash7_k, cudaFuncAttributeMaxDynamicSharedMemorySize, 90112);
        attr_set = true;
    }

    dim3 blk(256);
    prep_all_k<<<4417, blk>>>(x, Wq, Wk, Wv, Wvec, Wg, Wo, bq, bk, bv);
    // qkv (384) + vec-proj (768) fused
    gemm_qkvvec_k<<<1152, blk>>>(
        (const __nv_bfloat16*)xbp, (const __nv_bfloat16*)wqkvp, (const float*)bqkvp,
        (const __nv_bfloat16*)wvecp, qbp, kbp, vbp, projbp);
    // invariants
    inv_k<<<2048, blk>>>(adot, anrm);
    // attention
    flash7_k<<<dim3(16, 8, 4), blk, 90112>>>();
    // Wo (384) + gate (128) fused
    gemm_ogate_k<<<512, blk>>>(
        (const __nv_bfloat16*)xoutbp, (const __nv_bfloat16*)wop, bo,
        (const __nv_bfloat16*)invbp, (const __nv_bfloat16*)wgp, bg,
        obp, gatep);
    final_k<<<2048, blk>>>(x, out);
}

// round 17
// speedup vs baseline: 1.2703x; 1.0157x over previous
#include <cuda_runtime.h>
#include <cuda_bf16.h>
#include <math.h>
#include <stdint.h>

// ---------------- scratch (static device memory; no allocations) ----------------
__device__ __nv_bfloat16 g_xb[8192 * 1024];
__device__ __nv_bfloat16 g_wqkv[768 * 256];
__device__ float         g_bqkv[768];
__device__ __nv_bfloat16 g_wvecb[512 * 256];
__device__ __nv_bfloat16 g_wgb[256 * 512];
__device__ __nv_bfloat16 g_wob[768 * 256];
__device__ __nv_bfloat16 g_qb[8192 * 256];
__device__ __nv_bfloat16 g_kb[8192 * 256];
__device__ __nv_bfloat16 g_vb[8192 * 256];
__device__ __nv_bfloat16 g_projb[24576 * 512];
__device__ __nv_bfloat16 g_invb[8192 * 512];
__device__ __nv_bfloat16 g_xoutb[8192 * 256];
__device__ __nv_bfloat16 g_dotb[8192 * 256];
__device__ __nv_bfloat16 g_normb[8192 * 256];
__device__ __nv_bfloat16 g_gateb[8192 * 256];
__device__ __nv_bfloat16 g_vaggrb[8192 * 768];
__device__ __nv_bfloat16 g_ob[8192 * 768];

// ---------------- helpers ----------------
__device__ __forceinline__ uint32_t pack_bf2(float lo, float hi) {
    uint32_t r;
    asm("cvt.rn.bf16x2.f32 %0, %1, %2;" : "=r"(r) : "f"(hi), "f"(lo));
    return r;
}
__device__ __forceinline__ float2 unpack_bf2(uint32_t u) {
    __nv_bfloat162 h = *reinterpret_cast<__nv_bfloat162*>(&u);
    return __bfloat1622float2(h);
}
__device__ __forceinline__ void mma_bf16(float* c,
    uint32_t a0, uint32_t a1, uint32_t a2, uint32_t a3,
    uint32_t b0, uint32_t b1)
{
    asm volatile("mma.sync.aligned.m16n8k16.row.col.f32.bf16.bf16.f32 "
        "{%0,%1,%2,%3}, {%4,%5,%6,%7}, {%8,%9}, {%0,%1,%2,%3};"
        : "+f"(c[0]), "+f"(c[1]), "+f"(c[2]), "+f"(c[3])
        : "r"(a0), "r"(a1), "r"(a2), "r"(a3), "r"(b0), "r"(b1));
}
__device__ __forceinline__ void ldsm4(uint32_t& r0, uint32_t& r1, uint32_t& r2, uint32_t& r3,
                                      const void* p)
{
    uint32_t a = (uint32_t)__cvta_generic_to_shared(p);
    asm volatile("ldmatrix.sync.aligned.m8n8.x4.shared.b16 {%0,%1,%2,%3}, [%4];"
        : "=r"(r0), "=r"(r1), "=r"(r2), "=r"(r3) : "r"(a));
}
__device__ __forceinline__ void ldsm4t(uint32_t& r0, uint32_t& r1, uint32_t& r2, uint32_t& r3,
                                       const void* p)
{
    uint32_t a = (uint32_t)__cvta_generic_to_shared(p);
    asm volatile("ldmatrix.sync.aligned.m8n8.x4.trans.shared.b16 {%0,%1,%2,%3}, [%4];"
        : "=r"(r0), "=r"(r1), "=r"(r2), "=r"(r3) : "r"(a));
}
__device__ __forceinline__ void cpa16(uint32_t dst, const void* src) {
    asm volatile("cp.async.cg.shared.global [%0], [%1], 16;" :: "r"(dst), "l"(src));
}
__device__ __forceinline__ void cpa_commit() {
    asm volatile("cp.async.commit_group;");
}
template <int N>
__device__ __forceinline__ void cpa_wait() {
    asm volatile("cp.async.wait_group %0;" :: "n"(N));
}

// ---------------- fused prep: x -> bf16, weights -> bf16 (32B/thread) ----------------
__device__ __forceinline__ void cvt4(__nv_bfloat16* dst, const float* src) {
    float4 f = *(const float4*)src;
    uint32_t* d = (uint32_t*)dst;
    d[0] = pack_bf2(f.x, f.y);
    d[1] = pack_bf2(f.z, f.w);
}
__device__ __forceinline__ void cvt8(__nv_bfloat16* dst, const float* src) {
    cvt4(dst, src);
    cvt4(dst + 4, src + 4);
}
__global__ __launch_bounds__(256) void prep_all_k(
    const float* __restrict__ x,
    const float* __restrict__ Wq, const float* __restrict__ Wk, const float* __restrict__ Wv,
    const float* __restrict__ Wvec, const float* __restrict__ Wg, const float* __restrict__ Wo,
    const float* __restrict__ bq, const float* __restrict__ bk, const float* __restrict__ bv)
{
    int bid = blockIdx.x;
    if (bid < 4096) {
        size_t base = (size_t)bid * 2048 + threadIdx.x * 8;
        cvt8(g_xb + base, x + base);
        return;
    }
    long i = (long)((bid - 4096) * 256 + threadIdx.x) << 3;
    if (i < 65536)        cvt8(g_wqkv + i, Wq + i);
    else if (i < 131072)  cvt8(g_wqkv + i, Wk + (i - 65536));
    else if (i < 196608)  cvt8(g_wqkv + i, Wv + (i - 131072));
    else if (i < 327680)  cvt8(g_wvecb + (i - 196608), Wvec + (i - 196608));
    else if (i < 458752)  cvt8(g_wgb + (i - 327680), Wg + (i - 327680));
    else if (i < 655360)  cvt8(g_wob + (i - 458752), Wo + (i - 458752));
    else if (i < 656128) {
        int j = (int)(i - 655360);
        const float* src;
        float* dst = g_bqkv + j;
        if (j < 256)      src = bq + j;
        else if (j < 512) src = bk + (j - 256);
        else              src = bv + (j - 512);
        *(float4*)dst = *(const float4*)src;
        *(float4*)(dst + 4) = *(const float4*)(src + 4);
    }
}

// ---------------- bf16 cp.async GEMM body ----------------
template <int ROWMAP, int OUT>
__device__ __forceinline__ void gemm_body(
    uint32_t (*SA)[128][20], uint32_t (*SB)[128][20],
    int bn_blk, int bm_blk,
    const __nv_bfloat16* __restrict__ Ab, const __nv_bfloat16* __restrict__ Wb,
    const float* __restrict__ bias, void* __restrict__ Cv,
    void* __restrict__ Cv2, void* __restrict__ Cv3,
    int K, int lda, int ldc)
{
    const int tid = threadIdx.x;
    const int w = tid >> 5, lane = tid & 31;
    const int l4 = lane >> 2, lm4 = lane & 3, sel = lane >> 3;
    const int wr = w >> 2, wc = w & 3;
    const int bm = bm_blk << 7, bn = bn_blk << 7;

    const int r0 = tid >> 2, off = tid & 3;
    const __nv_bfloat16 *pa0, *pa1;
    if (ROWMAP == 0) {
        pa0 = Ab + (size_t)(bm + r0) * lda + off * 8;
        pa1 = Ab + (size_t)(bm + r0 + 64) * lda + off * 8;
    } else {
        int g0 = bm + r0, m0 = g0 / 3, c0 = g0 - 3 * m0;
        int g1 = bm + r0 + 64, m1 = g1 / 3, c1 = g1 - 3 * m1;
        pa0 = Ab + (size_t)m0 * 1024 + (size_t)(c0 + 1) * 256 + off * 8;
        pa1 = Ab + (size_t)m1 * 1024 + (size_t)(c1 + 1) * 256 + off * 8;
    }
    const __nv_bfloat16* pb0 = Wb + (size_t)(bn + r0) * K + off * 8;
    const __nv_bfloat16* pb1 = Wb + (size_t)(bn + r0 + 64) * K + off * 8;

    const uint32_t saA = (uint32_t)__cvta_generic_to_shared(&SA[0][0][0]);
    const uint32_t saB = (uint32_t)__cvta_generic_to_shared(&SB[0][0][0]);
    const uint32_t dA0 = saA + (r0 * 20 + off * 4) * 4;
    const uint32_t dA1 = saA + ((r0 + 64) * 20 + off * 4) * 4;
    const uint32_t dB0 = saB + (r0 * 20 + off * 4) * 4;
    const uint32_t dB1 = saB + ((r0 + 64) * 20 + off * 4) * 4;
    const uint32_t stB = 2560 * 4;

    float acc[4][4][4];
#pragma unroll
    for (int mt = 0; mt < 4; mt++)
#pragma unroll
        for (int nt = 0; nt < 4; nt++)
#pragma unroll
            for (int e = 0; e < 4; e++) acc[mt][nt][e] = 0.f;

    const int niter = K >> 5;

#pragma unroll
    for (int st = 0; st < 2; st++) {
        int k0 = st << 5;
        cpa16(dA0 + st * stB, pa0 + k0);
        cpa16(dA1 + st * stB, pa1 + k0);
        cpa16(dB0 + st * stB, pb0 + k0);
        cpa16(dB1 + st * stB, pb1 + k0);
        cpa_commit();
    }

    for (int it = 0; it < niter; it++) {
        if (it + 1 < niter) cpa_wait<1>(); else cpa_wait<0>();
        __syncthreads();
        const int st = it & 1;

#pragma unroll
        for (int ks = 0; ks < 2; ks++) {
            uint32_t af[4][4];
#pragma unroll
            for (int mt = 0; mt < 4; mt++)
                ldsm4(af[mt][0], af[mt][1], af[mt][2], af[mt][3],
                      &SA[st][wr * 64 + mt * 16 + (lane & 15)][ks * 8 + (lane >> 4) * 4]);
            uint32_t bf[4][2];
#pragma unroll
            for (int jp = 0; jp < 2; jp++) {
                uint32_t b0, b1, b2, b3;
                ldsm4(b0, b1, b2, b3,
                      &SB[st][wc * 32 + (jp * 2 + (sel >> 1)) * 8 + (lane & 7)][ks * 8 + (sel & 1) * 4]);
                bf[jp * 2][0] = b0; bf[jp * 2][1] = b1;
                bf[jp * 2 + 1][0] = b2; bf[jp * 2 + 1][1] = b3;
            }
#pragma unroll
            for (int mt = 0; mt < 4; mt++)
#pragma unroll
                for (int nt = 0; nt < 4; nt++)
                    mma_bf16(acc[mt][nt], af[mt][0], af[mt][1], af[mt][2], af[mt][3],
                             bf[nt][0], bf[nt][1]);
        }
        __syncthreads();
        if (it + 2 < niter) {
            int k0 = (it + 2) << 5;
            cpa16(dA0 + st * stB, pa0 + k0);
            cpa16(dA1 + st * stB, pa1 + k0);
            cpa16(dB0 + st * stB, pb0 + k0);
            cpa16(dB1 + st * stB, pb1 + k0);
            cpa_commit();
        }
    }

    const float qscale = 0.17677669529663687f;
#pragma unroll
    for (int mt = 0; mt < 4; mt++) {
#pragma unroll
        for (int nt = 0; nt < 4; nt++) {
            int c = bn + wc * 32 + nt * 8 + lm4 * 2;
            float bx = 0.f, by = 0.f;
            if (bias) { bx = bias[c]; by = bias[c + 1]; }
#pragma unroll
            for (int half = 0; half < 2; half++) {
                int r = bm + wr * 64 + mt * 16 + l4 + half * 8;
                float vx = acc[mt][nt][half * 2 + 0] + bx;
                float vy = acc[mt][nt][half * 2 + 1] + by;
                if (OUT == 5) {
                    vx = 1.f / (1.f + __expf(-vx));
                    vy = 1.f / (1.f + __expf(-vy));
                    ((uint32_t*)Cv)[((size_t)r * ldc + c) >> 1] = pack_bf2(vx, vy);
                } else if (OUT == 1) {
                    ((uint32_t*)Cv)[((size_t)r * ldc + c) >> 1] = pack_bf2(vx, vy);
                } else {  // OUT == 4: qkv split
                    int third = c >> 8, lc = c & 255;
                    void* dst = (third == 0) ? Cv : (third == 1 ? Cv2 : Cv3);
                    if (third == 0) { vx *= qscale; vy *= qscale; }
                    ((uint32_t*)dst)[((size_t)r * 256 + lc) >> 1] = pack_bf2(vx, vy);
                }
            }
        }
    }
}

// ---------------- fused GEMM launch 1: qkv (384) + vec-proj (768) ----------------
__global__ __launch_bounds__(256, 2) void gemm_qkvvec_k(
    const __nv_bfloat16* __restrict__ xb, const __nv_bfloat16* __restrict__ wqkv,
    const float* __restrict__ bqkv, const __nv_bfloat16* __restrict__ wvec,
    void* qb, void* kbv, void* vb, void* projb)
{
    __shared__ uint32_t SA[2][128][20];
    __shared__ uint32_t SB[2][128][20];
    int bid = blockIdx.x;
    if (bid < 384) {
        gemm_body<0, 4>(SA, SB, bid % 6, bid / 6, xb, wqkv, bqkv,
                        qb, kbv, vb, 256, 1024, 256);
    } else {
        int b2 = bid - 384;
        gemm_body<1, 1>(SA, SB, b2 % 4, b2 / 4, xb, wvec, nullptr,
                        projb, nullptr, nullptr, 256, 0, 512);
    }
}

// ---------------- fused GEMM launch 2: Wo (384) + gate (128) ----------------
__global__ __launch_bounds__(256, 2) void gemm_ogate_k(
    const __nv_bfloat16* __restrict__ xoutb, const __nv_bfloat16* __restrict__ wob,
    const float* __restrict__ bo, const __nv_bfloat16* __restrict__ invb,
    const __nv_bfloat16* __restrict__ wgb, const float* __restrict__ bg,
    void* ob, void* gateb)
{
    __shared__ uint32_t SA[2][128][20];
    __shared__ uint32_t SB[2][128][20];
    int bid = blockIdx.x;
    if (bid < 384) {
        gemm_body<0, 1>(SA, SB, bid % 6, bid / 6, xoutb, wob, bo,
                        ob, nullptr, nullptr, 256, 256, 768);
    } else {
        int b2 = bid - 384;
        gemm_body<0, 5>(SA, SB, b2 % 2, b2 / 2, invb, wgb, bg,
                        gateb, nullptr, nullptr, 512, 512, 256);
    }
}

// ---------------- invariants (dot/norm stored bf16) ----------------
__global__ __launch_bounds__(256) void inv_k(
    const float* __restrict__ alpha_dot, const float* __restrict__ alpha_norm)
{
    int idx = blockIdx.x * 256 + threadIdx.x;
    int m = idx >> 6, j = (idx & 63) << 2;
    const uint32_t* xb32 = (const uint32_t*)g_xb;
    float d0 = 0.f, d1 = 0.f, d2 = 0.f, d3 = 0.f;
    float n0 = 0.f, n1 = 0.f, n2 = 0.f, n3 = 0.f;
#pragma unroll
    for (int c = 0; c < 3; c++) {
        const uint32_t* pr = (const uint32_t*)(g_projb + (size_t)(m * 3 + c) * 512);
        uint32_t a0 = pr[(j >> 1)], a1 = pr[(j >> 1) + 1];
        uint32_t b0 = pr[128 + (j >> 1)], b1 = pr[129 + (j >> 1)];
        float2 fa0 = unpack_bf2(a0), fa1 = unpack_bf2(a1);
        float2 fb0 = unpack_bf2(b0), fb1 = unpack_bf2(b1);
        d0 += fa0.x * fb0.x; d1 += fa0.y * fb0.y;
        d2 += fa1.x * fb1.x; d3 += fa1.y * fb1.y;
        uint32_t x0 = xb32[((size_t)m * 1024 + 256 + c * 256 + j) >> 1];
        uint32_t x1 = xb32[(((size_t)m * 1024 + 256 + c * 256 + j) >> 1) + 1];
        float2 fx0 = unpack_bf2(x0), fx1 = unpack_bf2(x1);
        n0 += fx0.x * fx0.x; n1 += fx0.y * fx0.y;
        n2 += fx1.x * fx1.x; n3 += fx1.y * fx1.y;
    }
    n0 = sqrtf(n0); n1 = sqrtf(n1); n2 = sqrtf(n2); n3 = sqrtf(n3);
    uint32_t* db = (uint32_t*)g_dotb;
    uint32_t* nb = (uint32_t*)g_normb;
    size_t o4 = ((size_t)m * 256 + j) >> 1;
    db[o4]     = pack_bf2(d0, d1);
    db[o4 + 1] = pack_bf2(d2, d3);
    nb[o4]     = pack_bf2(n0, n1);
    nb[o4 + 1] = pack_bf2(n2, n3);
    float ad = alpha_dot[0], an = alpha_norm[0];
    uint32_t* inv32 = (uint32_t*)g_invb;
    inv32[((size_t)m * 512 + j) >> 1]       = pack_bf2(ad * d0, ad * d1);
    inv32[(((size_t)m * 512 + j) >> 1) + 1] = pack_bf2(ad * d2, ad * d3);
    inv32[((size_t)m * 512 + 256 + j) >> 1]       = pack_bf2(an * n0, an * n1);
    inv32[(((size_t)m * 512 + 256 + j) >> 1) + 1] = pack_bf2(an * n2, an * n3);
}

// ---------------- flash attention v8: chunked softmax, 2 CTAs/SM ----------------
// BQ=128, grid (16, 8, 4), 256 threads (8 warps); each warp: 16 q-rows x all keys.
// Per 64-key tile, keys processed in 4 chunks of 16: S-mma -> exp -> PV-mma,
// shrinking the live register set (s[8]+pa[4] instead of s[32]+pa[16]) so two
// CTAs fit per SM (16 warps -> latency hiding). 4-stage cp.async ring unchanged.
__global__ __launch_bounds__(256, 2) void flash8_k()
{
    extern __shared__ __align__(16) char raw[];
    const uint32_t smem_base = (uint32_t)__cvta_generic_to_shared(raw);
    uint32_t (*bufu)[66] = (uint32_t(*)[66])raw;

    const int qt = blockIdx.x, h = blockIdx.y, b = blockIdx.z;
    const int tid = threadIdx.x;
    const int w = tid >> 5, lane = tid & 31;
    const int l4 = lane >> 2, lm4 = lane & 3, sel = lane >> 3;
    const int r1 = w * 16 + l4;

    uint32_t qf[2][4];
    {
        const uint32_t* qb = (const uint32_t*)g_qb;
        const uint32_t* q1 = qb + (size_t)(b * 2048 + qt * 128 + r1) * 128 + h * 16;
        const uint32_t* q2 = q1 + 8 * 128;
        qf[0][0] = q1[lm4];     qf[0][1] = q2[lm4];
        qf[0][2] = q1[lm4 + 4]; qf[0][3] = q2[lm4 + 4];
        qf[1][0] = q1[8 + lm4];     qf[1][1] = q2[8 + lm4];
        qf[1][2] = q1[8 + lm4 + 4]; qf[1][3] = q2[8 + lm4 + 4];
    }

    float l1 = 0.f, l2 = 0.f;
    float o[16][4];
#pragma unroll
    for (int nt = 0; nt < 16; nt++)
#pragma unroll
        for (int e = 0; e < 4; e++) o[nt][e] = 0.f;

    const int krow = tid >> 2, kseg = tid & 3;
    const uint32_t* kbg = (const uint32_t*)g_kb;
    const uint32_t* vbg = (const uint32_t*)g_vb;
    const uint32_t* xbg = (const uint32_t*)g_xb;
    const uint32_t kdst0 = smem_base + (krow * 20 + kseg * 4) * 4;
    const uint32_t vdst0 = smem_base + 5120 + (krow * 68 + kseg * 16) * 4;

    auto issue_tile = [&](int kt2) {
        int tok = b * 2048 + kt2 * 64 + krow;
        uint32_t so = (uint32_t)(kt2 & 3) * 22528;
        cpa16(kdst0 + so, kbg + (size_t)tok * 128 + h * 16 + kseg * 4);
        const uint32_t* vsrc;
        if (kseg == 0) vsrc = vbg + (size_t)tok * 128 + h * 16;
        else           vsrc = xbg + (size_t)tok * 512 + 128 + (kseg - 1) * 128 + h * 16;
#pragma unroll
        for (int i = 0; i < 4; i++)
            cpa16(vdst0 + so + i * 16, vsrc + i * 4);
        cpa_commit();
    };

    issue_tile(0);
    issue_tile(1);
    issue_tile(2);

    for (int kt = 0; kt < 32; kt++) {
        cpa_wait<2>();
        __syncthreads();
        if (kt + 3 < 32) issue_tile(kt + 3);
        else cpa_commit();

        const char* stage = raw + (kt & 3) * 22528;
        const char* Kst = stage;            // [64][20] u32
        const char* Vst = stage + 5120;     // [64][68] u32

        // process the 64-key tile in 4 chunks of 16 keys
#pragma unroll
        for (int jp = 0; jp < 4; jp++) {
            // ---- S chunk: 16 rows x 16 keys ----
            float s0[4] = {0.f, 0.f, 0.f, 0.f};
            float s1[4] = {0.f, 0.f, 0.f, 0.f};
#pragma unroll
            for (int ks = 0; ks < 2; ks++) {
                int rowE = (jp * 2 + (sel >> 1)) * 8 + (lane & 7);
                int col = ks * 8 + (sel & 1) * 4;
                uint32_t b0, b1, b2, b3;
                ldsm4(b0, b1, b2, b3, Kst + rowE * 80 + col * 4);
                mma_bf16(s0, qf[ks][0], qf[ks][1], qf[ks][2], qf[ks][3], b0, b1);
                mma_bf16(s1, qf[ks][0], qf[ks][1], qf[ks][2], qf[ks][3], b2, b3);
            }

            // ---- exp + pack ----
            float p00 = __expf(s0[0]), p01 = __expf(s0[1]);
            float p02 = __expf(s0[2]), p03 = __expf(s0[3]);
            float p10 = __expf(s1[0]), p11 = __expf(s1[1]);
            float p12 = __expf(s1[2]), p13 = __expf(s1[3]);
            l1 += p00 + p01 + p10 + p11;
            l2 += p02 + p03 + p12 + p13;
            uint32_t pa0 = pack_bf2(p00, p01);
            uint32_t pa1 = pack_bf2(p02, p03);
            uint32_t pa2 = pack_bf2(p10, p11);
            uint32_t pa3 = pack_bf2(p12, p13);

            // ---- PV over this 16-key chunk ----
#pragma unroll
            for (int jj = 0; jj < 8; jj++) {
                int vrow = jp * 16 + (sel & 1) * 8 + (lane & 7);
                int vcol = jj * 8 + (sel >> 1) * 4;
                uint32_t b0, b1, b2, b3;
                ldsm4t(b0, b1, b2, b3, Vst + vrow * 272 + vcol * 4);
                mma_bf16(o[2 * jj + 0], pa0, pa1, pa2, pa3, b0, b1);
                mma_bf16(o[2 * jj + 1], pa0, pa1, pa2, pa3, b2, b3);
            }
        }
    }

    // ---- row-sum reduce (warp-local) ----
    l1 += __shfl_xor_sync(0xffffffffu, l1, 1);
    l1 += __shfl_xor_sync(0xffffffffu, l1, 2);
    l2 += __shfl_xor_sync(0xffffffffu, l2, 1);
    l2 += __shfl_xor_sync(0xffffffffu, l2, 2);
    float w1 = 1.f / l1, w2 = 1.f / l2;

    // ---- two-phase staged writeout through smem ----
#pragma unroll
    for (int ph = 0; ph < 2; ph++) {
        __syncthreads();
        if ((w >> 2) == ph) {
            int lr1 = (w & 3) * 16 + l4, lr2 = lr1 + 8;
#pragma unroll
            for (int nt = 0; nt < 16; nt++) {
                bufu[lr1][nt * 4 + lm4] = pack_bf2(o[nt][0] * w1, o[nt][1] * w1);
                bufu[lr2][nt * 4 + lm4] = pack_bf2(o[nt][2] * w2, o[nt][3] * w2);
            }
        }
        __syncthreads();
        int r = tid >> 2, qtr = tid & 3;
        int tok = b * 2048 + qt * 128 + ph * 64 + r;
        if (qtr == 0) {
            uint32_t* dst = (uint32_t*)g_xoutb + (size_t)tok * 128 + h * 16;
#pragma unroll
            for (int i = 0; i < 16; i++)
                dst[i] = bufu[r][i];
        } else {
            int c = qtr - 1;
            uint32_t* dst = (uint32_t*)g_vaggrb + (((size_t)tok * 768 + c * 256 + h * 32) >> 1);
#pragma unroll
            for (int i = 0; i < 16; i++)
                dst[i] = bufu[r][qtr * 16 + i];
        }
    }
}

// ---------------- final elementwise combine ----------------
__global__ __launch_bounds__(256) void final_k(const float* __restrict__ x, float* __restrict__ out)
{
    int idx = blockIdx.x * blockDim.x + threadIdx.x;
    if (idx >= 8192 * 64) return;
    int m = idx >> 6, j = (idx & 63) << 2;

    const uint32_t* ob = (const uint32_t*)g_ob;
    size_t base = (size_t)m * 768;
    uint32_t u;
    u = ob[(base + j) >> 1];       float2 o1a = unpack_bf2(u);
    u = ob[((base + j) >> 1) + 1]; float2 o1b = unpack_bf2(u);
    u = ob[(base + 256 + j) >> 1];       float2 o2a = unpack_bf2(u);
    u = ob[((base + 256 + j) >> 1) + 1]; float2 o2b = unpack_bf2(u);
    u = ob[(base + 512 + j) >> 1];       float2 o3a = unpack_bf2(u);
    u = ob[((base + 512 + j) >> 1) + 1]; float2 o3b = unpack_bf2(u);

    const uint32_t* db = (const uint32_t*)g_dotb;
    const uint32_t* nb = (const uint32_t*)g_normb;
    size_t o4 = ((size_t)m * 256 + j) >> 1;
    float2 vda = unpack_bf2(db[o4]), vdb = unpack_bf2(db[o4 + 1]);
    float2 vna = unpack_bf2(nb[o4]), vnb = unpack_bf2(nb[o4 + 1]);

    float4 r;
    r.x = vda.x * o1a.x + vna.x * o2a.x + o3a.x;
    r.y = vda.y * o1a.y + vna.y * o2a.y + o3a.y;
    r.z = vdb.x * o1b.x + vnb.x * o2b.x + o3b.x;
    r.w = vdb.y * o1b.y + vnb.y * o2b.y + o3b.y;
    *(float4*)(out + (size_t)m * 1024 + j) = r;

    const uint32_t* gb = (const uint32_t*)g_gateb;
    u = gb[o4];     float2 ga = unpack_bf2(u);
    u = gb[o4 + 1]; float2 gbv = unpack_bf2(u);
    const uint32_t* vab = (const uint32_t*)g_vaggrb;
#pragma unroll
    for (int c = 0; c < 3; c++) {
        size_t xi = (size_t)m * 1024 + 256 + c * 256 + j;
        u = vab[(base + c * 256 + j) >> 1];       float2 va = unpack_bf2(u);
        u = vab[((base + c * 256 + j) >> 1) + 1]; float2 vb = unpack_bf2(u);
        float4 xv = *(const float4*)(x + xi);
        float4 rr;
        rr.x = ga.x * va.x + xv.x;
        rr.y = ga.y * va.y + xv.y;
        rr.z = gbv.x * vb.x + xv.z;
        rr.w = gbv.y * vb.y + xv.w;
        *(float4*)(out + xi) = rr;
    }
}

// ---------------- launch ----------------
extern "C" void kernel_launch(void* const* d_in, const int* in_sizes, int n_in,
                              void* d_out, int out_size)
{
    const float* x    = (const float*)d_in[0];
    const float* Wq   = (const float*)d_in[1];
    const float* bq   = (const float*)d_in[2];
    const float* Wk   = (const float*)d_in[3];
    const float* bk   = (const float*)d_in[4];
    const float* Wv   = (const float*)d_in[5];
    const float* bv   = (const float*)d_in[6];
    const float* Wvec = (const float*)d_in[7];
    const float* Wo   = (const float*)d_in[8];
    const float* bo   = (const float*)d_in[9];
    const float* Wg   = (const float*)d_in[10];
    const float* bg   = (const float*)d_in[11];
    const float* adot = (const float*)d_in[12];
    const float* anrm = (const float*)d_in[13];
    float* out = (float*)d_out;

    void *xbp, *wqkvp, *bqkvp, *wvecp, *wgp, *wop;
    void *qbp, *kbp, *vbp, *projbp, *invbp, *xoutbp, *gatep, *obp;
    cudaGetSymbolAddress(&xbp, g_xb);
    cudaGetSymbolAddress(&wqkvp, g_wqkv);
    cudaGetSymbolAddress(&bqkvp, g_bqkv);
    cudaGetSymbolAddress(&wvecp, g_wvecb);
    cudaGetSymbolAddress(&wgp, g_wgb);
    cudaGetSymbolAddress(&wop, g_wob);
    cudaGetSymbolAddress(&qbp, g_qb);
    cudaGetSymbolAddress(&kbp, g_kb);
    cudaGetSymbolAddress(&vbp, g_vb);
    cudaGetSymbolAddress(&projbp, g_projb);
    cudaGetSymbolAddress(&invbp, g_invb);
    cudaGetSymbolAddress(&xoutbp, g_xoutb);
    cudaGetSymbolAddress(&gatep, g_gateb);
    cudaGetSymbolAddress(&obp, g_ob);

    static bool attr_set = false;
    if (!attr_set) {
        cudaFuncSetAttribute(flash8_k, cudaFuncAttributeMaxDynamicSharedMemorySize, 90112);
        attr_set = true;
    }

    dim3 blk(256);
    prep_all_k<<<4417, blk>>>(x, Wq, Wk, Wv, Wvec, Wg, Wo, bq, bk, bv);
    gemm_qkvvec_k<<<1152, blk>>>(
        (const __nv_bfloat16*)xbp, (const __nv_bfloat16*)wqkvp, (const float*)bqkvp,
        (const __nv_bfloat16*)wvecp, qbp, kbp, vbp, projbp);
    inv_k<<<2048, blk>>>(adot, anrm);
    flash8_k<<<dim3(16, 8, 4), blk, 90112>>>();
    gemm_ogate_k<<<512, blk>>>(
        (const __nv_bfloat16*)xoutbp, (const __nv_bfloat16*)wop, bo,
        (const __nv_bfloat16*)invbp, (const __nv_bfloat16*)wgp, bg,
        obp, gatep);
    final_k<<<2048, blk>>>(x, out);
}